// round 1
// baseline (speedup 1.0000x reference)
#include <cuda_runtime.h>
#include <cuda_bf16.h>

#define N_NODES_MAX 50048
#define N_EDGES_MAX 800000
#define N_GRAPHS 64
#define HID1 256
#define HID2 128

// ---------------- scratch (static __device__, no allocation) ----------------
__device__ float g_bufA[50000 * 256];   // xw / hw
__device__ float g_bufB[50000 * 256];   // h1 / h2
__device__ int   g_degout[N_NODES_MAX];
__device__ int   g_degin [N_NODES_MAX];
__device__ float g_invo  [N_NODES_MAX];
__device__ float g_invi  [N_NODES_MAX];
__device__ int   g_rowptr[N_NODES_MAX + 1];
__device__ int   g_cursor[N_NODES_MAX];
__device__ int   g_csr   [N_EDGES_MAX];
__device__ float g_gsum  [N_GRAPHS * HID2];
__device__ int   g_gcnt  [N_GRAPHS];

// ---------------- init ----------------
__global__ void zero_init(int n) {
    int i = blockIdx.x * blockDim.x + threadIdx.x;
    if (i < n) { g_degout[i] = 0; g_degin[i] = 0; g_cursor[i] = 0; }
    if (i < N_GRAPHS * HID2) g_gsum[i] = 0.f;
    if (i < N_GRAPHS) g_gcnt[i] = 0;
}

// ---------------- degree histogram ----------------
__global__ void hist_kernel(const int* __restrict__ src, const int* __restrict__ dst, int E) {
    int e = blockIdx.x * blockDim.x + threadIdx.x;
    if (e < E) {
        atomicAdd(&g_degout[src[e]], 1);
        atomicAdd(&g_degin [dst[e]], 1);
    }
}

// ---------------- exclusive scan over deg_in -> rowptr (single block) ----------------
__global__ void scan_rowptr(int n) {
    __shared__ int warp_sums[32];
    __shared__ int s_carry;
    int tid = threadIdx.x;            // 1024
    int lane = tid & 31, wid = tid >> 5;
    if (tid == 0) s_carry = 0;
    __syncthreads();
    for (int base = 0; base < n; base += 1024) {
        int i = base + tid;
        int v = (i < n) ? g_degin[i] : 0;
        int x = v;
        #pragma unroll
        for (int o = 1; o < 32; o <<= 1) {
            int y = __shfl_up_sync(0xFFFFFFFFu, x, o);
            if (lane >= o) x += y;
        }
        if (lane == 31) warp_sums[wid] = x;
        __syncthreads();
        if (tid < 32) {
            int w = warp_sums[tid];
            #pragma unroll
            for (int o = 1; o < 32; o <<= 1) {
                int y = __shfl_up_sync(0xFFFFFFFFu, w, o);
                if (tid >= o) w += y;
            }
            warp_sums[tid] = w;
        }
        __syncthreads();
        int prefix = (wid > 0) ? warp_sums[wid - 1] : 0;
        int total  = warp_sums[31];
        int excl   = x - v + prefix + s_carry;
        if (i < n) g_rowptr[i] = excl;
        __syncthreads();
        if (tid == 0) s_carry += total;
        __syncthreads();
    }
    if (tid == 0) g_rowptr[n] = s_carry;
}

// ---------------- inv sqrt degrees ----------------
__global__ void make_inv(int n) {
    int i = blockIdx.x * blockDim.x + threadIdx.x;
    if (i < n) {
        g_invo[i] = rsqrtf((float)max(g_degout[i], 1));
        g_invi[i] = rsqrtf((float)max(g_degin [i], 1));
    }
}

// ---------------- CSR fill (edges grouped by dst) ----------------
__global__ void fill_csr(const int* __restrict__ src, const int* __restrict__ dst, int E) {
    int e = blockIdx.x * blockDim.x + threadIdx.x;
    if (e < E) {
        int d = dst[e];
        int pos = atomicAdd(&g_cursor[d], 1);
        g_csr[g_rowptr[d] + pos] = src[e];
    }
}

// ---------------- row-scaled GEMM: C[M,N] = (A[M,K] * invo[M]) @ B[K,N] ----------------
// BM=128, BN=128, BK=16, TM=8, TN=8, 256 threads
__global__ void __launch_bounds__(256)
gemm_rowscale(const float* __restrict__ A, const float* __restrict__ B,
              float* __restrict__ C, int M, int N, int K)
{
    const int BM = 128, BN = 128, BK = 16, TM = 8, TN = 8;
    __shared__ float As[BK][BM + 4];
    __shared__ float Bs[BK][BN + 4];

    const int tid = threadIdx.x;
    const int tx = tid % (BN / TN);   // 0..15
    const int ty = tid / (BN / TN);   // 0..15
    const int rowBase = blockIdx.x * BM;
    const int colBase = blockIdx.y * BN;

    // A-load mapping: 2 passes of 64 rows, float4 per (row, quarter)
    const int a_r0 = tid >> 2;          // 0..63
    const int a_c  = (tid & 3) * 4;     // 0,4,8,12
    // B-load mapping: 2 passes of 8 rows, 32 float4 per row
    const int b_r0 = tid >> 5;          // 0..7
    const int b_c  = (tid & 31) * 4;    // 0..124

    float acc[TM][TN];
    #pragma unroll
    for (int i = 0; i < TM; i++)
        #pragma unroll
        for (int j = 0; j < TN; j++) acc[i][j] = 0.f;

    for (int k0 = 0; k0 < K; k0 += BK) {
        #pragma unroll
        for (int p = 0; p < 2; ++p) {
            int r = a_r0 + p * 64;
            int gr = rowBase + r;
            float4 v = make_float4(0.f, 0.f, 0.f, 0.f);
            float s = 0.f;
            if (gr < M) {
                v = *(const float4*)(A + (size_t)gr * K + k0 + a_c);
                s = g_invo[gr];
            }
            As[a_c + 0][r] = v.x * s;
            As[a_c + 1][r] = v.y * s;
            As[a_c + 2][r] = v.z * s;
            As[a_c + 3][r] = v.w * s;
        }
        #pragma unroll
        for (int p = 0; p < 2; ++p) {
            int r = b_r0 + p * 8;
            float4 v = *(const float4*)(B + (size_t)(k0 + r) * N + colBase + b_c);
            *(float4*)&Bs[r][b_c] = v;
        }
        __syncthreads();

        #pragma unroll
        for (int kk = 0; kk < BK; ++kk) {
            float a[TM], b[TN];
            #pragma unroll
            for (int i = 0; i < TM; i++) a[i] = As[kk][ty * TM + i];
            #pragma unroll
            for (int j = 0; j < TN; j++) b[j] = Bs[kk][tx * TN + j];
            #pragma unroll
            for (int i = 0; i < TM; i++)
                #pragma unroll
                for (int j = 0; j < TN; j++)
                    acc[i][j] = fmaf(a[i], b[j], acc[i][j]);
        }
        __syncthreads();
    }

    #pragma unroll
    for (int i = 0; i < TM; i++) {
        int gr = rowBase + ty * TM + i;
        if (gr < M) {
            #pragma unroll
            for (int j4 = 0; j4 < TN / 4; j4++) {
                float4 v = make_float4(acc[i][j4 * 4 + 0], acc[i][j4 * 4 + 1],
                                       acc[i][j4 * 4 + 2], acc[i][j4 * 4 + 3]);
                *(float4*)(C + (size_t)gr * N + colBase + tx * TN + j4 * 4) = v;
            }
        }
    }
}

// ---------------- CSR gather SpMM + epilogue: Y[n] = relu(invi[n]*sum_{u in N(n)} X[u] + b) ----------------
template<int F4, int ROWS>
__global__ void spmm_csr(const float4* __restrict__ X, const float* __restrict__ bias,
                         float4* __restrict__ Y, int n)
{
    int row = blockIdx.x * ROWS + threadIdx.y;
    if (row >= n) return;
    int f = threadIdx.x;                 // 0..F4-1
    int s = g_rowptr[row], e = g_rowptr[row + 1];
    float4 acc = make_float4(0.f, 0.f, 0.f, 0.f);
    int i = s;
    for (; i + 1 < e; i += 2) {
        int u0 = g_csr[i], u1 = g_csr[i + 1];
        float4 v0 = X[(size_t)u0 * F4 + f];
        float4 v1 = X[(size_t)u1 * F4 + f];
        acc.x += v0.x + v1.x;
        acc.y += v0.y + v1.y;
        acc.z += v0.z + v1.z;
        acc.w += v0.w + v1.w;
    }
    if (i < e) {
        int u = g_csr[i];
        float4 v = X[(size_t)u * F4 + f];
        acc.x += v.x; acc.y += v.y; acc.z += v.z; acc.w += v.w;
    }
    float sc = g_invi[row];
    float4 b = *(const float4*)(bias + f * 4);
    float4 r;
    r.x = fmaxf(fmaf(acc.x, sc, b.x), 0.f);
    r.y = fmaxf(fmaf(acc.y, sc, b.y), 0.f);
    r.z = fmaxf(fmaf(acc.z, sc, b.z), 0.f);
    r.w = fmaxf(fmaf(acc.w, sc, b.w), 0.f);
    Y[(size_t)row * F4 + f] = r;
}

// ---------------- sorted-graph_id pooling (boundary-flush atomics only) ----------------
#define POOL_NB 128
__global__ void pool_accum(const float* __restrict__ h, const int* __restrict__ gid, int n)
{
    const int f = threadIdx.x;   // 128
    int base = blockIdx.x * POOL_NB;
    if (base >= n) return;
    int end = min(base + POOL_NB, n);
    float acc = 0.f; int cnt = 0;
    int cur = gid[base];
    for (int i = base; i < end; ++i) {
        int g = gid[i];
        if (g != cur) {
            atomicAdd(&g_gsum[cur * HID2 + f], acc);
            if (f == 0) atomicAdd(&g_gcnt[cur], cnt);
            acc = 0.f; cnt = 0; cur = g;
        }
        acc += h[(size_t)i * HID2 + f];
        cnt++;
    }
    atomicAdd(&g_gsum[cur * HID2 + f], acc);
    if (f == 0) atomicAdd(&g_gcnt[cur], cnt);
}

// ---------------- MLP head: [64,128]@[128,12]@[12,12]@[12,10] ----------------
__global__ void mlp_head(const float* __restrict__ Wc1, const float* __restrict__ bc1,
                         const float* __restrict__ Wc2, const float* __restrict__ bc2,
                         const float* __restrict__ Wc3, const float* __restrict__ bc3,
                         float* __restrict__ out)
{
    __shared__ float hg[N_GRAPHS * HID2];
    __shared__ float t1[N_GRAPHS * 12];
    __shared__ float t2[N_GRAPHS * 12];
    int tid = threadIdx.x;   // 768
    for (int i = tid; i < N_GRAPHS * HID2; i += 768) {
        int g = i >> 7;
        hg[i] = g_gsum[i] / (float)max(g_gcnt[g], 1);
    }
    __syncthreads();
    {
        int g = tid / 12, j = tid % 12;
        float a = bc1[j];
        #pragma unroll 8
        for (int k = 0; k < HID2; k++) a = fmaf(hg[g * HID2 + k], Wc1[k * 12 + j], a);
        t1[tid] = a;
    }
    __syncthreads();
    {
        int g = tid / 12, j = tid % 12;
        float a = bc2[j];
        #pragma unroll
        for (int k = 0; k < 12; k++) a = fmaf(t1[g * 12 + k], Wc2[k * 12 + j], a);
        t2[tid] = a;
    }
    __syncthreads();
    if (tid < N_GRAPHS * 10) {
        int g = tid / 10, j = tid % 10;
        float a = bc3[j];
        #pragma unroll
        for (int k = 0; k < 12; k++) a = fmaf(t2[g * 12 + k], Wc3[k * 10 + j], a);
        out[g * 10 + j] = a;
    }
}

// ---------------- launch ----------------
extern "C" void kernel_launch(void* const* d_in, const int* in_sizes, int n_in,
                              void* d_out, int out_size)
{
    const float* x   = (const float*)d_in[0];
    const int*   src = (const int*)  d_in[1];
    const int*   dst = (const int*)  d_in[2];
    const int*   gid = (const int*)  d_in[3];
    const float* W1  = (const float*)d_in[4];
    const float* b1  = (const float*)d_in[5];
    const float* W2  = (const float*)d_in[6];
    const float* b2  = (const float*)d_in[7];
    const float* Wc1 = (const float*)d_in[8];
    const float* bc1 = (const float*)d_in[9];
    const float* Wc2 = (const float*)d_in[10];
    const float* bc2 = (const float*)d_in[11];
    const float* Wc3 = (const float*)d_in[12];
    const float* bc3 = (const float*)d_in[13];
    float* out = (float*)d_out;

    const int n = in_sizes[0] / 128;   // nodes
    const int E = in_sizes[1];         // edges

    float *bufA, *bufB;
    cudaGetSymbolAddress((void**)&bufA, g_bufA);
    cudaGetSymbolAddress((void**)&bufB, g_bufB);

    zero_init<<<(n + 255) / 256, 256>>>(n);
    hist_kernel<<<(E + 255) / 256, 256>>>(src, dst, E);
    scan_rowptr<<<1, 1024>>>(n);
    make_inv<<<(n + 255) / 256, 256>>>(n);
    fill_csr<<<(E + 255) / 256, 256>>>(src, dst, E);

    // Layer 1: xw = (x*invo)@W1  [n,256]
    gemm_rowscale<<<dim3((n + 127) / 128, HID1 / 128), 256>>>(x, W1, bufA, n, HID1, 128);
    // h1 = relu(invi * A_gather(xw) + b1)
    spmm_csr<64, 4><<<(n + 3) / 4, dim3(64, 4)>>>((const float4*)bufA, b1, (float4*)bufB, n);

    // Layer 2: hw = (h1*invo)@W2  [n,128]
    gemm_rowscale<<<dim3((n + 127) / 128, HID2 / 128), 256>>>(bufB, W2, bufA, n, HID2, HID1);
    // h2 = relu(invi * A_gather(hw) + b2)  -> reuse bufB (stride 128)
    spmm_csr<32, 8><<<(n + 7) / 8, dim3(32, 8)>>>((const float4*)bufA, b2, (float4*)bufB, n);

    // mean pooling (graph_id sorted)
    pool_accum<<<(n + POOL_NB - 1) / POOL_NB, 128>>>(bufB, gid, n);

    // classifier head
    mlp_head<<<1, 768>>>(Wc1, bc1, Wc2, bc2, Wc3, bc3, out);
}

// round 2
// speedup vs baseline: 1.2666x; 1.2666x over previous
#include <cuda_runtime.h>
#include <cuda_bf16.h>

#define N_NODES_MAX 50048
#define N_EDGES_MAX 800000
#define N_GRAPHS 64
#define HID1 256
#define HID2 128

typedef unsigned long long u64;

// ---------------- scratch (static __device__, no allocation) ----------------
__device__ float g_bufA[50000 * 256];   // agg_x / hw
__device__ float g_bufB[50000 * 256];   // h1 / h2
__device__ int   g_degout[N_NODES_MAX];
__device__ int   g_degin [N_NODES_MAX];
__device__ float g_invo  [N_NODES_MAX];
__device__ float g_invi  [N_NODES_MAX];
__device__ int   g_rowptr[N_NODES_MAX + 1];
__device__ int   g_cursor[N_NODES_MAX];
__device__ int   g_csr   [N_EDGES_MAX];
__device__ float g_gsum  [N_GRAPHS * HID2];
__device__ int   g_gcnt  [N_GRAPHS];

// ---------------- f32x2 helpers ----------------
__device__ __forceinline__ u64 pack2(float lo, float hi) {
    u64 r; asm("mov.b64 %0, {%1, %2};" : "=l"(r) : "f"(lo), "f"(hi)); return r;
}
__device__ __forceinline__ void fma2(u64& d, u64 a, u64 b) {
    asm("fma.rn.f32x2 %0, %1, %2, %0;" : "+l"(d) : "l"(a), "l"(b));
}
__device__ __forceinline__ void unpack2(float& lo, float& hi, u64 v) {
    asm("mov.b64 {%0, %1}, %2;" : "=f"(lo), "=f"(hi) : "l"(v));
}
__device__ __forceinline__ void cp_async16(void* smem_dst, const void* gptr) {
    unsigned saddr = (unsigned)__cvta_generic_to_shared(smem_dst);
    asm volatile("cp.async.cg.shared.global [%0], [%1], 16;" :: "r"(saddr), "l"(gptr));
}
__device__ __forceinline__ void cp_commit() { asm volatile("cp.async.commit_group;"); }
__device__ __forceinline__ void cp_wait0()  { asm volatile("cp.async.wait_group 0;"); }

// ---------------- init ----------------
__global__ void zero_init(int n) {
    int i = blockIdx.x * blockDim.x + threadIdx.x;
    if (i < n) { g_degout[i] = 0; g_degin[i] = 0; g_cursor[i] = 0; }
    if (i < N_GRAPHS * HID2) g_gsum[i] = 0.f;
    if (i < N_GRAPHS) g_gcnt[i] = 0;
}

__global__ void hist_kernel(const int* __restrict__ src, const int* __restrict__ dst, int E) {
    int e = blockIdx.x * blockDim.x + threadIdx.x;
    if (e < E) {
        atomicAdd(&g_degout[src[e]], 1);
        atomicAdd(&g_degin [dst[e]], 1);
    }
}

__global__ void scan_rowptr(int n) {
    __shared__ int warp_sums[32];
    __shared__ int s_carry;
    int tid = threadIdx.x;            // 1024
    int lane = tid & 31, wid = tid >> 5;
    if (tid == 0) s_carry = 0;
    __syncthreads();
    for (int base = 0; base < n; base += 1024) {
        int i = base + tid;
        int v = (i < n) ? g_degin[i] : 0;
        int x = v;
        #pragma unroll
        for (int o = 1; o < 32; o <<= 1) {
            int y = __shfl_up_sync(0xFFFFFFFFu, x, o);
            if (lane >= o) x += y;
        }
        if (lane == 31) warp_sums[wid] = x;
        __syncthreads();
        if (tid < 32) {
            int w = warp_sums[tid];
            #pragma unroll
            for (int o = 1; o < 32; o <<= 1) {
                int y = __shfl_up_sync(0xFFFFFFFFu, w, o);
                if (tid >= o) w += y;
            }
            warp_sums[tid] = w;
        }
        __syncthreads();
        int prefix = (wid > 0) ? warp_sums[wid - 1] : 0;
        int total  = warp_sums[31];
        int excl   = x - v + prefix + s_carry;
        if (i < n) g_rowptr[i] = excl;
        __syncthreads();
        if (tid == 0) s_carry += total;
        __syncthreads();
    }
    if (tid == 0) g_rowptr[n] = s_carry;
}

__global__ void make_inv(int n) {
    int i = blockIdx.x * blockDim.x + threadIdx.x;
    if (i < n) {
        g_invo[i] = rsqrtf((float)max(g_degout[i], 1));
        g_invi[i] = rsqrtf((float)max(g_degin [i], 1));
    }
}

__global__ void fill_csr(const int* __restrict__ src, const int* __restrict__ dst, int E) {
    int e = blockIdx.x * blockDim.x + threadIdx.x;
    if (e < E) {
        int d = dst[e];
        int pos = atomicAdd(&g_cursor[d], 1);
        g_csr[g_rowptr[d] + pos] = src[e];
    }
}

// ---------------- GEMM: C = epilogue(A @ W)  (f32x2, cp.async double-buffered) ----------------
// BM=128, BN=128, BK=16, TM=8, TN=8, 256 threads
// epilogue: RELU ? max(scale[row]*acc + bias[col], 0) : scale[row]*acc
template<bool RELU>
__global__ void __launch_bounds__(256, 2)
gemm_f32x2(const float* __restrict__ A, const float* __restrict__ W,
           const float* __restrict__ scale, const float* __restrict__ bias,
           float* __restrict__ C, int M, int N, int K)
{
    const int BM = 128, BN = 128, BK = 16, TM = 8, TN = 8;
    __shared__ float As[2][BK][BM + 4];
    __shared__ float Bs[2][BK][BN + 4];

    const int tid = threadIdx.x;
    const int tx = tid & 15;          // 0..15
    const int ty = tid >> 4;          // 0..15
    const int rowBase = blockIdx.x * BM;
    const int colBase = blockIdx.y * BN;

    // A reg-staging mapping: 2 passes of 64 rows, float4 per (row, quarter)
    const int a_r0 = tid >> 2;          // 0..63
    const int a_c  = (tid & 3) * 4;     // 0,4,8,12
    // B cp.async mapping: id = tid + p*256; row = id>>5 (0..15), col = (id&31)*4
    const int T = K / BK;

    u64 accp[TM][TN / 2];
    #pragma unroll
    for (int i = 0; i < TM; i++)
        #pragma unroll
        for (int j = 0; j < TN / 2; j++) accp[i][j] = 0ull;

    float4 aReg[2];

    // ---- prologue: tile 0 ----
    {
        #pragma unroll
        for (int p = 0; p < 2; ++p) {
            int gr = rowBase + a_r0 + p * 64;
            aReg[p] = (gr < M) ? *(const float4*)(A + (size_t)gr * K + a_c)
                               : make_float4(0.f, 0.f, 0.f, 0.f);
        }
        #pragma unroll
        for (int p = 0; p < 2; ++p) {
            int id = tid + p * 256;
            int r = id >> 5, c = (id & 31) * 4;
            cp_async16(&Bs[0][r][c], W + (size_t)r * N + colBase + c);
        }
        cp_commit();
        #pragma unroll
        for (int p = 0; p < 2; ++p) {
            int r = a_r0 + p * 64;
            As[0][a_c + 0][r] = aReg[p].x;
            As[0][a_c + 1][r] = aReg[p].y;
            As[0][a_c + 2][r] = aReg[p].z;
            As[0][a_c + 3][r] = aReg[p].w;
        }
        cp_wait0();
        __syncthreads();
    }

    for (int t = 0; t < T; ++t) {
        const int cur = t & 1, nxt = cur ^ 1;
        const bool more = (t + 1 < T);
        if (more) {
            int k0 = (t + 1) * BK;
            #pragma unroll
            for (int p = 0; p < 2; ++p) {
                int gr = rowBase + a_r0 + p * 64;
                aReg[p] = (gr < M) ? *(const float4*)(A + (size_t)gr * K + k0 + a_c)
                                   : make_float4(0.f, 0.f, 0.f, 0.f);
            }
            #pragma unroll
            for (int p = 0; p < 2; ++p) {
                int id = tid + p * 256;
                int r = id >> 5, c = (id & 31) * 4;
                cp_async16(&Bs[nxt][r][c], W + (size_t)(k0 + r) * N + colBase + c);
            }
            cp_commit();
        }

        #pragma unroll
        for (int kk = 0; kk < BK; ++kk) {
            float4 a0 = *(const float4*)&As[cur][kk][ty * TM];
            float4 a1 = *(const float4*)&As[cur][kk][ty * TM + 4];
            ulonglong2 q0 = *(const ulonglong2*)&Bs[cur][kk][tx * TN];
            ulonglong2 q1 = *(const ulonglong2*)&Bs[cur][kk][tx * TN + 4];
            u64 bp[4] = {q0.x, q0.y, q1.x, q1.y};
            u64 ap[8];
            ap[0] = pack2(a0.x, a0.x); ap[1] = pack2(a0.y, a0.y);
            ap[2] = pack2(a0.z, a0.z); ap[3] = pack2(a0.w, a0.w);
            ap[4] = pack2(a1.x, a1.x); ap[5] = pack2(a1.y, a1.y);
            ap[6] = pack2(a1.z, a1.z); ap[7] = pack2(a1.w, a1.w);
            #pragma unroll
            for (int i = 0; i < TM; i++)
                #pragma unroll
                for (int j = 0; j < TN / 2; j++)
                    fma2(accp[i][j], ap[i], bp[j]);
        }

        if (more) {
            #pragma unroll
            for (int p = 0; p < 2; ++p) {
                int r = a_r0 + p * 64;
                As[nxt][a_c + 0][r] = aReg[p].x;
                As[nxt][a_c + 1][r] = aReg[p].y;
                As[nxt][a_c + 2][r] = aReg[p].z;
                As[nxt][a_c + 3][r] = aReg[p].w;
            }
            cp_wait0();
        }
        __syncthreads();
    }

    // ---- epilogue ----
    float4 bv0 = make_float4(0.f, 0.f, 0.f, 0.f), bv1 = bv0;
    if (RELU) {
        bv0 = *(const float4*)(bias + colBase + tx * TN);
        bv1 = *(const float4*)(bias + colBase + tx * TN + 4);
    }
    #pragma unroll
    for (int i = 0; i < TM; i++) {
        int gr = rowBase + ty * TM + i;
        if (gr < M) {
            float s = scale[gr];
            float v[8];
            #pragma unroll
            for (int j = 0; j < 4; j++) unpack2(v[2 * j], v[2 * j + 1], accp[i][j]);
            float4 o0, o1;
            if (RELU) {
                o0.x = fmaxf(fmaf(v[0], s, bv0.x), 0.f);
                o0.y = fmaxf(fmaf(v[1], s, bv0.y), 0.f);
                o0.z = fmaxf(fmaf(v[2], s, bv0.z), 0.f);
                o0.w = fmaxf(fmaf(v[3], s, bv0.w), 0.f);
                o1.x = fmaxf(fmaf(v[4], s, bv1.x), 0.f);
                o1.y = fmaxf(fmaf(v[5], s, bv1.y), 0.f);
                o1.z = fmaxf(fmaf(v[6], s, bv1.z), 0.f);
                o1.w = fmaxf(fmaf(v[7], s, bv1.w), 0.f);
            } else {
                o0.x = v[0] * s; o0.y = v[1] * s; o0.z = v[2] * s; o0.w = v[3] * s;
                o1.x = v[4] * s; o1.y = v[5] * s; o1.z = v[6] * s; o1.w = v[7] * s;
            }
            *(float4*)(C + (size_t)gr * N + colBase + tx * TN)     = o0;
            *(float4*)(C + (size_t)gr * N + colBase + tx * TN + 4) = o1;
        }
    }
}

// ---------------- CSR gather SpMM ----------------
// SCALE_SRC: acc += X[u] * invo[u]  (else plain sum)
// EPI: Y = relu(acc*invi + bias)    (else Y = acc)
template<int F4, int ROWS, bool SCALE_SRC, bool EPI>
__global__ void spmm_csr(const float4* __restrict__ X, const float* __restrict__ bias,
                         float4* __restrict__ Y, int n)
{
    int row = blockIdx.x * ROWS + threadIdx.y;
    if (row >= n) return;
    int f = threadIdx.x;                 // 0..F4-1
    int s = g_rowptr[row], e = g_rowptr[row + 1];
    float4 acc = make_float4(0.f, 0.f, 0.f, 0.f);
    int i = s;
    for (; i + 1 < e; i += 2) {
        int u0 = g_csr[i], u1 = g_csr[i + 1];
        float4 v0 = X[(size_t)u0 * F4 + f];
        float4 v1 = X[(size_t)u1 * F4 + f];
        if (SCALE_SRC) {
            float s0 = g_invo[u0], s1 = g_invo[u1];
            acc.x = fmaf(v0.x, s0, acc.x); acc.x = fmaf(v1.x, s1, acc.x);
            acc.y = fmaf(v0.y, s0, acc.y); acc.y = fmaf(v1.y, s1, acc.y);
            acc.z = fmaf(v0.z, s0, acc.z); acc.z = fmaf(v1.z, s1, acc.z);
            acc.w = fmaf(v0.w, s0, acc.w); acc.w = fmaf(v1.w, s1, acc.w);
        } else {
            acc.x += v0.x + v1.x;
            acc.y += v0.y + v1.y;
            acc.z += v0.z + v1.z;
            acc.w += v0.w + v1.w;
        }
    }
    if (i < e) {
        int u = g_csr[i];
        float4 v = X[(size_t)u * F4 + f];
        if (SCALE_SRC) {
            float s0 = g_invo[u];
            acc.x = fmaf(v.x, s0, acc.x); acc.y = fmaf(v.y, s0, acc.y);
            acc.z = fmaf(v.z, s0, acc.z); acc.w = fmaf(v.w, s0, acc.w);
        } else {
            acc.x += v.x; acc.y += v.y; acc.z += v.z; acc.w += v.w;
        }
    }
    if (EPI) {
        float sc = g_invi[row];
        float4 b = *(const float4*)(bias + f * 4);
        float4 r;
        r.x = fmaxf(fmaf(acc.x, sc, b.x), 0.f);
        r.y = fmaxf(fmaf(acc.y, sc, b.y), 0.f);
        r.z = fmaxf(fmaf(acc.z, sc, b.z), 0.f);
        r.w = fmaxf(fmaf(acc.w, sc, b.w), 0.f);
        Y[(size_t)row * F4 + f] = r;
    } else {
        Y[(size_t)row * F4 + f] = acc;
    }
}

// ---------------- sorted-graph_id pooling ----------------
#define POOL_NB 32
__global__ void pool_accum(const float* __restrict__ h, const int* __restrict__ gid, int n)
{
    const int f = threadIdx.x;   // 128
    int base = blockIdx.x * POOL_NB;
    if (base >= n) return;
    int end = min(base + POOL_NB, n);
    float acc = 0.f; int cnt = 0;
    int cur = gid[base];
    for (int i = base; i < end; ++i) {
        int g = gid[i];
        if (g != cur) {
            atomicAdd(&g_gsum[cur * HID2 + f], acc);
            if (f == 0) atomicAdd(&g_gcnt[cur], cnt);
            acc = 0.f; cnt = 0; cur = g;
        }
        acc += h[(size_t)i * HID2 + f];
        cnt++;
    }
    atomicAdd(&g_gsum[cur * HID2 + f], acc);
    if (f == 0) atomicAdd(&g_gcnt[cur], cnt);
}

// ---------------- MLP head ----------------
__global__ void mlp_head(const float* __restrict__ Wc1, const float* __restrict__ bc1,
                         const float* __restrict__ Wc2, const float* __restrict__ bc2,
                         const float* __restrict__ Wc3, const float* __restrict__ bc3,
                         float* __restrict__ out)
{
    __shared__ float hg[N_GRAPHS * HID2];
    __shared__ float t1[N_GRAPHS * 12];
    __shared__ float t2[N_GRAPHS * 12];
    int tid = threadIdx.x;   // 768
    for (int i = tid; i < N_GRAPHS * HID2; i += 768) {
        int g = i >> 7;
        hg[i] = g_gsum[i] / (float)max(g_gcnt[g], 1);
    }
    __syncthreads();
    {
        int g = tid / 12, j = tid % 12;
        float a = bc1[j];
        #pragma unroll 8
        for (int k = 0; k < HID2; k++) a = fmaf(hg[g * HID2 + k], Wc1[k * 12 + j], a);
        t1[tid] = a;
    }
    __syncthreads();
    {
        int g = tid / 12, j = tid % 12;
        float a = bc2[j];
        #pragma unroll
        for (int k = 0; k < 12; k++) a = fmaf(t1[g * 12 + k], Wc2[k * 12 + j], a);
        t2[tid] = a;
    }
    __syncthreads();
    if (tid < N_GRAPHS * 10) {
        int g = tid / 10, j = tid % 10;
        float a = bc3[j];
        #pragma unroll
        for (int k = 0; k < 12; k++) a = fmaf(t2[g * 12 + k], Wc3[k * 10 + j], a);
        out[g * 10 + j] = a;
    }
}

// ---------------- launch ----------------
extern "C" void kernel_launch(void* const* d_in, const int* in_sizes, int n_in,
                              void* d_out, int out_size)
{
    const float* x   = (const float*)d_in[0];
    const int*   src = (const int*)  d_in[1];
    const int*   dst = (const int*)  d_in[2];
    const int*   gid = (const int*)  d_in[3];
    const float* W1  = (const float*)d_in[4];
    const float* b1  = (const float*)d_in[5];
    const float* W2  = (const float*)d_in[6];
    const float* b2  = (const float*)d_in[7];
    const float* Wc1 = (const float*)d_in[8];
    const float* bc1 = (const float*)d_in[9];
    const float* Wc2 = (const float*)d_in[10];
    const float* bc2 = (const float*)d_in[11];
    const float* Wc3 = (const float*)d_in[12];
    const float* bc3 = (const float*)d_in[13];
    float* out = (float*)d_out;

    const int n = in_sizes[0] / 128;   // nodes
    const int E = in_sizes[1];         // edges

    float *bufA, *bufB;
    cudaGetSymbolAddress((void**)&bufA, g_bufA);
    cudaGetSymbolAddress((void**)&bufB, g_bufB);

    float *invo_p, *invi_p;
    cudaGetSymbolAddress((void**)&invo_p, g_invo);
    cudaGetSymbolAddress((void**)&invi_p, g_invi);

    zero_init<<<(n + 255) / 256, 256>>>(n);
    hist_kernel<<<(E + 255) / 256, 256>>>(src, dst, E);
    scan_rowptr<<<1, 1024>>>(n);
    make_inv<<<(n + 255) / 256, 256>>>(n);
    fill_csr<<<(E + 255) / 256, 256>>>(src, dst, E);

    // Layer 1 (aggregate-first: IN_DIM=128 < HID1=256):
    //   aggx = segsum((x*invo)[src])  [n,128]
    spmm_csr<32, 8, true, false><<<(n + 7) / 8, dim3(32, 8)>>>((const float4*)x, nullptr, (float4*)bufA, n);
    //   h1 = relu(invi * (aggx @ W1) + b1)  [n,256]
    gemm_f32x2<true><<<dim3((n + 127) / 128, HID1 / 128), 256>>>(bufA, W1, invi_p, b1, bufB, n, HID1, 128);

    // Layer 2 (W-first: HID1=256 > HID2=128):
    //   hw = invo * (h1 @ W2)  [n,128]
    gemm_f32x2<false><<<dim3((n + 127) / 128, HID2 / 128), 256>>>(bufB, W2, invo_p, nullptr, bufA, n, HID2, HID1);
    //   h2 = relu(invi * segsum(hw[src]) + b2)  [n,128]
    spmm_csr<32, 8, false, true><<<(n + 7) / 8, dim3(32, 8)>>>((const float4*)bufA, b2, (float4*)bufB, n);

    // mean pooling (graph_id sorted)
    pool_accum<<<(n + POOL_NB - 1) / POOL_NB, 128>>>(bufB, gid, n);

    // classifier head
    mlp_head<<<1, 768>>>(Wc1, bc1, Wc2, bc2, Wc3, bc3, out);
}

// round 4
// speedup vs baseline: 1.5157x; 1.1967x over previous
#include <cuda_runtime.h>
#include <cuda_bf16.h>
#include <cstdint>

#if defined(__CUDA_ARCH_FEAT_SM103_ALL) || defined(__CUDA_ARCH_FEAT_SM100_ALL) || defined(__CUDA_ARCH_FEAT_SM101_ALL)
#define HAS_TCGEN05 1
#else
#define HAS_TCGEN05 0
#endif

#define N_NODES_MAX 50048
#define N_EDGES_MAX 800000
#define N_GRAPHS 64
#define HID1 256
#define HID2 128

typedef unsigned long long u64;
typedef unsigned int u32;

// ---------------- scratch (static __device__, no allocation) ----------------
__device__ u32   g_aggx_hi[N_NODES_MAX * 128];
__device__ u32   g_aggx_lo[N_NODES_MAX * 128];
__device__ float g_aggx_f [N_NODES_MAX * 128];
__device__ u32   g_h1_hi  [N_NODES_MAX * 256];
__device__ u32   g_h1_lo  [N_NODES_MAX * 256];
__device__ float g_h1_f   [N_NODES_MAX * 256];
__device__ float g_hw     [N_NODES_MAX * 128];
__device__ float g_h2     [N_NODES_MAX * 128];
__device__ u32   g_w1t_hi [256 * 128];
__device__ u32   g_w1t_lo [256 * 128];
__device__ u32   g_w2t_hi [128 * 256];
__device__ u32   g_w2t_lo [128 * 256];
__device__ int   g_degout[N_NODES_MAX];
__device__ int   g_degin [N_NODES_MAX];
__device__ float g_invo  [N_NODES_MAX];
__device__ float g_invi  [N_NODES_MAX];
__device__ int   g_rowptr[N_NODES_MAX + 1];
__device__ int   g_cursor[N_NODES_MAX];
__device__ int   g_csr   [N_EDGES_MAX];
__device__ float g_gsum  [N_GRAPHS * HID2];
__device__ int   g_gcnt  [N_GRAPHS];

// ---------------- generic helpers (safe on all targets) ----------------
__device__ __forceinline__ u32 tf32_rna(float x) {
    u32 r; asm("cvt.rna.tf32.f32 %0, %1;" : "=r"(r) : "f"(x)); return r;
}
__device__ __forceinline__ void split_tf32(float v, u32& hi, u32& lo) {
    hi = tf32_rna(v);
    lo = tf32_rna(v - __uint_as_float(hi));
}
__device__ __forceinline__ u64 pack2(float lo, float hi) {
    u64 r; asm("mov.b64 %0, {%1, %2};" : "=l"(r) : "f"(lo), "f"(hi)); return r;
}
__device__ __forceinline__ void fma2(u64& d, u64 a, u64 b) {
    asm("fma.rn.f32x2 %0, %1, %2, %0;" : "+l"(d) : "l"(a), "l"(b));
}
__device__ __forceinline__ void unpack2(float& lo, float& hi, u64 v) {
    asm("mov.b64 {%0, %1}, %2;" : "=f"(lo), "=f"(hi) : "l"(v));
}
__device__ __forceinline__ void cp_async16(void* smem_dst, const void* gptr) {
    unsigned saddr = (unsigned)__cvta_generic_to_shared(smem_dst);
    asm volatile("cp.async.cg.shared.global [%0], [%1], 16;" :: "r"(saddr), "l"(gptr));
}
__device__ __forceinline__ void cp_async16z(uint32_t saddr, const void* gptr, int bytes) {
    asm volatile("cp.async.cg.shared.global [%0], [%1], 16, %2;" :: "r"(saddr), "l"(gptr), "r"(bytes));
}
__device__ __forceinline__ void cp_commit() { asm volatile("cp.async.commit_group;"); }
__device__ __forceinline__ void cp_wait0()  { asm volatile("cp.async.wait_group 0;"); }

#define SWZ128(o) ((o) ^ (((o) >> 3) & 0x70))

// ---------------- preprocessing ----------------
__global__ void zero_init(int n) {
    int i = blockIdx.x * blockDim.x + threadIdx.x;
    if (i < n) { g_degout[i] = 0; g_degin[i] = 0; g_cursor[i] = 0; }
    if (i < N_GRAPHS * HID2) g_gsum[i] = 0.f;
    if (i < N_GRAPHS) g_gcnt[i] = 0;
}

__global__ void hist_kernel(const int* __restrict__ src, const int* __restrict__ dst, int E) {
    int e = blockIdx.x * blockDim.x + threadIdx.x;
    if (e < E) {
        atomicAdd(&g_degout[src[e]], 1);
        atomicAdd(&g_degin [dst[e]], 1);
    }
}

__global__ void scan_rowptr(int n) {
    __shared__ int warp_sums[32];
    __shared__ int s_carry;
    int tid = threadIdx.x;
    int lane = tid & 31, wid = tid >> 5;
    if (tid == 0) s_carry = 0;
    __syncthreads();
    for (int base = 0; base < n; base += 1024) {
        int i = base + tid;
        int v = (i < n) ? g_degin[i] : 0;
        int x = v;
        #pragma unroll
        for (int o = 1; o < 32; o <<= 1) {
            int y = __shfl_up_sync(0xFFFFFFFFu, x, o);
            if (lane >= o) x += y;
        }
        if (lane == 31) warp_sums[wid] = x;
        __syncthreads();
        if (tid < 32) {
            int w = warp_sums[tid];
            #pragma unroll
            for (int o = 1; o < 32; o <<= 1) {
                int y = __shfl_up_sync(0xFFFFFFFFu, w, o);
                if (tid >= o) w += y;
            }
            warp_sums[tid] = w;
        }
        __syncthreads();
        int prefix = (wid > 0) ? warp_sums[wid - 1] : 0;
        int total  = warp_sums[31];
        int excl   = x - v + prefix + s_carry;
        if (i < n) g_rowptr[i] = excl;
        __syncthreads();
        if (tid == 0) s_carry += total;
        __syncthreads();
    }
    if (tid == 0) g_rowptr[n] = s_carry;
}

__global__ void make_inv(int n) {
    int i = blockIdx.x * blockDim.x + threadIdx.x;
    if (i < n) {
        g_invo[i] = rsqrtf((float)max(g_degout[i], 1));
        g_invi[i] = rsqrtf((float)max(g_degin [i], 1));
    }
}

__global__ void fill_csr(const int* __restrict__ src, const int* __restrict__ dst, int E) {
    int e = blockIdx.x * blockDim.x + threadIdx.x;
    if (e < E) {
        int d = dst[e];
        int pos = atomicAdd(&g_cursor[d], 1);
        g_csr[g_rowptr[d] + pos] = src[e];
    }
}

// weight transpose + tf32 split
__global__ void wconv(const float* __restrict__ W1, const float* __restrict__ W2) {
    int i = blockIdx.x * blockDim.x + threadIdx.x;
    if (i < 128 * 256) {
        int k = i >> 8, nn = i & 255;
        u32 hi, lo; split_tf32(W1[i], hi, lo);
        g_w1t_hi[nn * 128 + k] = hi;
        g_w1t_lo[nn * 128 + k] = lo;
    }
    if (i < 256 * 128) {
        int k = i >> 7, nn = i & 127;
        u32 hi, lo; split_tf32(W2[i], hi, lo);
        g_w2t_hi[nn * 256 + k] = hi;
        g_w2t_lo[nn * 256 + k] = lo;
    }
}

// ---------------- CSR gather SpMM ----------------
__global__ void spmm_split(const float4* __restrict__ X, int n)
{
    int row = blockIdx.x * 8 + threadIdx.y;
    if (row >= n) return;
    int f = threadIdx.x;                 // 0..31
    int s = g_rowptr[row], e = g_rowptr[row + 1];
    float4 acc = make_float4(0.f, 0.f, 0.f, 0.f);
    int i = s;
    for (; i + 1 < e; i += 2) {
        int u0 = g_csr[i], u1 = g_csr[i + 1];
        float4 v0 = X[(size_t)u0 * 32 + f];
        float4 v1 = X[(size_t)u1 * 32 + f];
        float s0 = g_invo[u0], s1 = g_invo[u1];
        acc.x = fmaf(v0.x, s0, acc.x); acc.x = fmaf(v1.x, s1, acc.x);
        acc.y = fmaf(v0.y, s0, acc.y); acc.y = fmaf(v1.y, s1, acc.y);
        acc.z = fmaf(v0.z, s0, acc.z); acc.z = fmaf(v1.z, s1, acc.z);
        acc.w = fmaf(v0.w, s0, acc.w); acc.w = fmaf(v1.w, s1, acc.w);
    }
    if (i < e) {
        int u = g_csr[i];
        float4 v = X[(size_t)u * 32 + f];
        float s0 = g_invo[u];
        acc.x = fmaf(v.x, s0, acc.x); acc.y = fmaf(v.y, s0, acc.y);
        acc.z = fmaf(v.z, s0, acc.z); acc.w = fmaf(v.w, s0, acc.w);
    }
    uint4 hi, lo;
    split_tf32(acc.x, hi.x, lo.x);
    split_tf32(acc.y, hi.y, lo.y);
    split_tf32(acc.z, hi.z, lo.z);
    split_tf32(acc.w, hi.w, lo.w);
    ((uint4*)g_aggx_hi)[(size_t)row * 32 + f] = hi;
    ((uint4*)g_aggx_lo)[(size_t)row * 32 + f] = lo;
    ((float4*)g_aggx_f)[(size_t)row * 32 + f] = acc;
}

__global__ void spmm_plain(const float4* __restrict__ X, const float* __restrict__ bias,
                           float4* __restrict__ Y, int n)
{
    int row = blockIdx.x * 8 + threadIdx.y;
    if (row >= n) return;
    int f = threadIdx.x;
    int s = g_rowptr[row], e = g_rowptr[row + 1];
    float4 acc = make_float4(0.f, 0.f, 0.f, 0.f);
    int i = s;
    for (; i + 1 < e; i += 2) {
        int u0 = g_csr[i], u1 = g_csr[i + 1];
        float4 v0 = X[(size_t)u0 * 32 + f];
        float4 v1 = X[(size_t)u1 * 32 + f];
        acc.x += v0.x + v1.x;
        acc.y += v0.y + v1.y;
        acc.z += v0.z + v1.z;
        acc.w += v0.w + v1.w;
    }
    if (i < e) {
        int u = g_csr[i];
        float4 v = X[(size_t)u * 32 + f];
        acc.x += v.x; acc.y += v.y; acc.z += v.z; acc.w += v.w;
    }
    float sc = g_invi[row];
    float4 b = *(const float4*)(bias + f * 4);
    float4 r;
    r.x = fmaxf(fmaf(acc.x, sc, b.x), 0.f);
    r.y = fmaxf(fmaf(acc.y, sc, b.y), 0.f);
    r.z = fmaxf(fmaf(acc.z, sc, b.z), 0.f);
    r.w = fmaxf(fmaf(acc.w, sc, b.w), 0.f);
    Y[(size_t)row * 32 + f] = r;
}

// ================== tcgen05 3xTF32 GEMM (sm_103a-only body) ==================
#define SM_TMEM 0
#define SM_MBAR 8
#define SM_BIAS 64
#define SM_AHI  1024
#define SM_ALO  (1024 + 16384)
#define SM_BHI  (1024 + 32768)
#define SM_BLO  (1024 + 49152)
#define GEMM_SMEM (1024 + 65536)

#if HAS_TCGEN05
static constexpr uint64_t SMEM_DESC_BASE_SW128 =
    (uint64_t(2) << 61) | (uint64_t(1) << 46) | (uint64_t(64) << 32) | (uint64_t(1) << 16);
#define MK_DESC(a) (SMEM_DESC_BASE_SW128 | ((uint64_t)((a) >> 4) & 0x3FFF))

#define TC_ALLOC(sm, n)  asm volatile("tcgen05.alloc.cta_group::1.sync.aligned.shared::cta.b32 [%0], %1;" :: "r"((uint32_t)(sm)), "r"((uint32_t)(n)) : "memory")
#define TC_RELINQ()      asm volatile("tcgen05.relinquish_alloc_permit.cta_group::1.sync.aligned;")
#define TC_DEALLOC(t, n) asm volatile("tcgen05.dealloc.cta_group::1.sync.aligned.b32 %0, %1;" :: "r"(t), "r"((uint32_t)(n)))
#define TC_COMMIT(mb)    asm volatile("tcgen05.commit.cta_group::1.mbarrier::arrive::one.shared::cluster.b64 [%0];" :: "r"((uint32_t)(mb)) : "memory")
#define TC_FENCE_AFTER() asm volatile("tcgen05.fence::after_thread_sync;" ::: "memory")
#define TC_FENCE_BEFORE() asm volatile("tcgen05.fence::before_thread_sync;" ::: "memory")
#define TC_WAIT_LD()     asm volatile("tcgen05.wait::ld.sync.aligned;" ::: "memory")
#define MBAR_INIT(mb, c) asm volatile("mbarrier.init.shared.b64 [%0], %1;" :: "r"((uint32_t)(mb)), "r"((uint32_t)(c)) : "memory")
#define MBAR_INVAL(mb)   asm volatile("mbarrier.inval.shared.b64 [%0];" :: "r"((uint32_t)(mb)) : "memory")
#define FENCE_ASYNC()    asm volatile("fence.proxy.async.shared::cta;" ::: "memory")

#define MBAR_WAIT(mb, ph) do { \
    uint32_t _mb = (uint32_t)(mb); uint32_t _p = (uint32_t)(ph); uint32_t _done; \
    asm volatile("{\n\t.reg .pred p;\n\tmbarrier.try_wait.parity.acquire.cta.shared::cta.b64 p, [%1], %2;\n\tselp.b32 %0, 1, 0, p;\n\t}" \
        : "=r"(_done) : "r"(_mb), "r"(_p) : "memory"); \
    if (!_done) { \
        asm volatile("{\n\t.reg .pred P1;\nWL_%=:\n\tmbarrier.try_wait.parity.acquire.cta.shared::cta.b64 P1, [%0], %1, 0x989680;\n\t@P1 bra.uni WD_%=;\n\tbra.uni WL_%=;\nWD_%=:\n\t}" \
            :: "r"(_mb), "r"(_p) : "memory"); \
    } \
} while (0)

#define TC_LD_X32(r, ta) \
    asm volatile("tcgen05.ld.sync.aligned.32x32b.x32.b32 " \
        "{%0, %1, %2, %3, %4, %5, %6, %7, %8, %9, %10, %11, %12, %13, %14, %15, " \
        " %16, %17, %18, %19, %20, %21, %22, %23, %24, %25, %26, %27, %28, %29, %30, %31}, [%32];" \
        : "=r"((r)[0]), "=r"((r)[1]), "=r"((r)[2]), "=r"((r)[3]), "=r"((r)[4]), "=r"((r)[5]), "=r"((r)[6]), "=r"((r)[7]), \
          "=r"((r)[8]), "=r"((r)[9]), "=r"((r)[10]), "=r"((r)[11]), "=r"((r)[12]), "=r"((r)[13]), "=r"((r)[14]), "=r"((r)[15]), \
          "=r"((r)[16]), "=r"((r)[17]), "=r"((r)[18]), "=r"((r)[19]), "=r"((r)[20]), "=r"((r)[21]), "=r"((r)[22]), "=r"((r)[23]), \
          "=r"((r)[24]), "=r"((r)[25]), "=r"((r)[26]), "=r"((r)[27]), "=r"((r)[28]), "=r"((r)[29]), "=r"((r)[30]), "=r"((r)[31]) \
        : "r"(ta))

__device__ __forceinline__ uint32_t elect_one() {
    uint32_t pred;
    asm volatile("{\n\t.reg .pred p;\n\telect.sync _|p, 0xFFFFFFFF;\n\tselp.b32 %0, 1, 0, p;\n\t}" : "=r"(pred));
    return pred;
}
__device__ __forceinline__ void mma_tf32(uint32_t d, uint64_t a, uint64_t b, uint32_t idesc, bool en) {
    uint32_t e = en ? 1u : 0u;
    asm volatile("{\n\t.reg .pred p;\n\tsetp.ne.u32 p, %5, 0;\n\t"
                 "tcgen05.mma.cta_group::1.kind::tf32 [%0], %1, %2, %3, {%4, %4, %4, %4}, p;\n\t}"
                 :: "r"(d), "l"(a), "l"(b), "r"(idesc), "r"(0u), "r"(e) : "memory");
}
#endif  // HAS_TCGEN05

// C[128x128 tile] = (Ahi+Alo) @ (Bhi+Blo)^T ; A[M,K] hi/lo tf32, B as [N][K].
// MODE 0: Of = scale[row]*acc ; MODE 1: relu(scale*acc+bias) -> split to Ohi/Olo AND NOT Of.
template<int KCH, int MODE>
__global__ void __launch_bounds__(128)
gemm_tc(const u32* __restrict__ Ahi, const u32* __restrict__ Alo,
        const u32* __restrict__ Bhi, const u32* __restrict__ Blo,
        const float* __restrict__ scale, const float* __restrict__ bias,
        u32* __restrict__ Ohi, u32* __restrict__ Olo, float* __restrict__ Of,
        int M, int NTOT)
{
#if HAS_TCGEN05
    extern __shared__ __align__(1024) char smem[];
    const uint32_t sb = (uint32_t)__cvta_generic_to_shared(smem);
    const int tid = threadIdx.x;
    const int wid = tid >> 5, lane = tid & 31;
    const int K = KCH * 32;
    const int rowBase = blockIdx.x * 128;
    const int colBase = blockIdx.y * 128;

    if (wid == 0) {
        TC_ALLOC(sb + SM_TMEM, 128);
        TC_RELINQ();
    }
    if (tid == 0) MBAR_INIT(sb + SM_MBAR, 1);
    if (MODE == 1) {
        *(float*)(smem + SM_BIAS + tid * 4) = bias[colBase + tid];
    }
    __syncthreads();
    uint32_t tmem;
    asm volatile("ld.shared.b32 %0, [%1];" : "=r"(tmem) : "r"(sb + SM_TMEM));

    // idesc: dtype F32, atype/btype TF32(2), N=128, M=128
    const uint32_t idesc = (1u << 4) | (2u << 7) | (2u << 10) | (16u << 17) | (8u << 24);

    for (int ch = 0; ch < KCH; ++ch) {
        const int k0 = ch * 32;
        #pragma unroll
        for (int i = 0; i < 8; ++i) {
            int t = tid + i * 128;
            int row = t >> 3;            // 0..127
            int c16 = t & 7;             // 16B unit within 128B row
            uint32_t dofs = SWZ128((uint32_t)(row * 128 + c16 * 16));
            int gr = rowBase + row;
            int abytes = (gr < M) ? 16 : 0;
            const u32* asrch = Ahi + (size_t)min(gr, M - 1) * K + k0 + c16 * 4;
            const u32* asrcl = Alo + (size_t)min(gr, M - 1) * K + k0 + c16 * 4;
            cp_async16z(sb + SM_AHI + dofs, asrch, abytes);
            cp_async16z(sb + SM_ALO + dofs, asrcl, abytes);
            const u32* bsrch = Bhi + (size_t)(colBase + row) * K + k0 + c16 * 4;
            const u32* bsrcl = Blo + (size_t)(colBase + row) * K + k0 + c16 * 4;
            cp_async16z(sb + SM_BHI + dofs, bsrch, 16);
            cp_async16z(sb + SM_BLO + dofs, bsrcl, 16);
        }
        cp_commit();
        cp_wait0();
        FENCE_ASYNC();
        __syncthreads();

        if (wid == 0) {
            TC_FENCE_AFTER();
            if (elect_one()) {
                uint64_t dah = MK_DESC(sb + SM_AHI);
                uint64_t dal = MK_DESC(sb + SM_ALO);
                uint64_t dbh = MK_DESC(sb + SM_BHI);
                uint64_t dbl = MK_DESC(sb + SM_BLO);
                #pragma unroll
                for (int ks = 0; ks < 4; ++ks)
                    mma_tf32(tmem, dah + ks * 2, dbh + ks * 2, idesc, !(ch == 0 && ks == 0));
                #pragma unroll
                for (int ks = 0; ks < 4; ++ks)
                    mma_tf32(tmem, dah + ks * 2, dbl + ks * 2, idesc, true);
                #pragma unroll
                for (int ks = 0; ks < 4; ++ks)
                    mma_tf32(tmem, dal + ks * 2, dbh + ks * 2, idesc, true);
                TC_COMMIT(sb + SM_MBAR);
            }
        }
        MBAR_WAIT(sb + SM_MBAR, ch & 1);
        __syncthreads();
    }
    TC_FENCE_AFTER();

    // epilogue: each warp reads its 32-lane subpartition
    const int gr = rowBase + wid * 32 + lane;
    const float s = (gr < M) ? scale[gr] : 0.f;
    #pragma unroll
    for (int g = 0; g < 4; ++g) {
        u32 r[32];
        TC_LD_X32(r, tmem + g * 32);
        TC_WAIT_LD();
        if (gr < M) {
            if (MODE == 1) {
                u32 hi[32], lo[32];
                float fv[32];
                #pragma unroll
                for (int c = 0; c < 32; ++c) {
                    float bv = *(const float*)(smem + SM_BIAS + (g * 32 + c) * 4);
                    float v = fmaxf(fmaf(__uint_as_float(r[c]), s, bv), 0.f);
                    split_tf32(v, hi[c], lo[c]);
                    fv[c] = v;
                }
                size_t ofs = (size_t)gr * NTOT + colBase + g * 32;
                #pragma unroll
                for (int q = 0; q < 8; ++q) {
                    *(uint4*)(Ohi + ofs + q * 4) = *(uint4*)&hi[q * 4];
                    *(uint4*)(Olo + ofs + q * 4) = *(uint4*)&lo[q * 4];
                }
                (void)fv;
            } else {
                float v[32];
                #pragma unroll
                for (int c = 0; c < 32; ++c) v[c] = __uint_as_float(r[c]) * s;
                size_t ofs = (size_t)gr * NTOT + colBase + g * 32;
                #pragma unroll
                for (int q = 0; q < 8; ++q)
                    *(float4*)(Of + ofs + q * 4) = *(float4*)&v[q * 4];
            }
        }
    }
    TC_FENCE_BEFORE();
    __syncthreads();
    if (tid == 0) MBAR_INVAL(sb + SM_MBAR);
    __syncthreads();
    if (wid == 0) TC_DEALLOC(tmem, 128);
#endif  // HAS_TCGEN05 (else: empty kernel — fallback GEMM does the work)
}

// ================== fallback f32x2 GEMM (active only when tcgen05 is NOT) ==================
// C = epilogue(A @ W), A[M,K] fp32, W[K,N] fp32 (original layout)
template<bool RELU>
__global__ void __launch_bounds__(256, 2)
gemm_fb(const float* __restrict__ A, const float* __restrict__ W,
        const float* __restrict__ scale, const float* __restrict__ bias,
        float* __restrict__ C, int M, int N, int K)
{
#if !HAS_TCGEN05
    const int BM = 128, BN = 128, BK = 16, TM = 8, TN = 8;
    __shared__ float As[2][BK][BM + 4];
    __shared__ float Bs[2][BK][BN + 4];

    const int tid = threadIdx.x;
    const int tx = tid & 15;
    const int ty = tid >> 4;
    const int rowBase = blockIdx.x * BM;
    const int colBase = blockIdx.y * BN;

    const int a_r0 = tid >> 2;
    const int a_c  = (tid & 3) * 4;
    const int T = K / BK;

    u64 accp[TM][TN / 2];
    #pragma unroll
    for (int i = 0; i < TM; i++)
        #pragma unroll
        for (int j = 0; j < TN / 2; j++) accp[i][j] = 0ull;

    float4 aReg[2];
    {
        #pragma unroll
        for (int p = 0; p < 2; ++p) {
            int gr = rowBase + a_r0 + p * 64;
            aReg[p] = (gr < M) ? *(const float4*)(A + (size_t)gr * K + a_c)
                               : make_float4(0.f, 0.f, 0.f, 0.f);
        }
        #pragma unroll
        for (int p = 0; p < 2; ++p) {
            int id = tid + p * 256;
            int r = id >> 5, c = (id & 31) * 4;
            cp_async16(&Bs[0][r][c], W + (size_t)r * N + colBase + c);
        }
        cp_commit();
        #pragma unroll
        for (int p = 0; p < 2; ++p) {
            int r = a_r0 + p * 64;
            As[0][a_c + 0][r] = aReg[p].x;
            As[0][a_c + 1][r] = aReg[p].y;
            As[0][a_c + 2][r] = aReg[p].z;
            As[0][a_c + 3][r] = aReg[p].w;
        }
        cp_wait0();
        __syncthreads();
    }

    for (int t = 0; t < T; ++t) {
        const int cur = t & 1, nxt = cur ^ 1;
        const bool more = (t + 1 < T);
        if (more) {
            int k0 = (t + 1) * BK;
            #pragma unroll
            for (int p = 0; p < 2; ++p) {
                int gr = rowBase + a_r0 + p * 64;
                aReg[p] = (gr < M) ? *(const float4*)(A + (size_t)gr * K + k0 + a_c)
                                   : make_float4(0.f, 0.f, 0.f, 0.f);
            }
            #pragma unroll
            for (int p = 0; p < 2; ++p) {
                int id = tid + p * 256;
                int r = id >> 5, c = (id & 31) * 4;
                cp_async16(&Bs[nxt][r][c], W + (size_t)(k0 + r) * N + colBase + c);
            }
            cp_commit();
        }

        #pragma unroll
        for (int kk = 0; kk < BK; ++kk) {
            float4 a0 = *(const float4*)&As[cur][kk][ty * TM];
            float4 a1 = *(const float4*)&As[cur][kk][ty * TM + 4];
            ulonglong2 q0 = *(const ulonglong2*)&Bs[cur][kk][tx * TN];
            ulonglong2 q1 = *(const ulonglong2*)&Bs[cur][kk][tx * TN + 4];
            u64 bp[4] = {q0.x, q0.y, q1.x, q1.y};
            u64 ap[8];
            ap[0] = pack2(a0.x, a0.x); ap[1] = pack2(a0.y, a0.y);
            ap[2] = pack2(a0.z, a0.z); ap[3] = pack2(a0.w, a0.w);
            ap[4] = pack2(a1.x, a1.x); ap[5] = pack2(a1.y, a1.y);
            ap[6] = pack2(a1.z, a1.z); ap[7] = pack2(a1.w, a1.w);
            #pragma unroll
            for (int i = 0; i < TM; i++)
                #pragma unroll
                for (int j = 0; j < TN / 2; j++)
                    fma2(accp[i][j], ap[i], bp[j]);
        }

        if (more) {
            #pragma unroll
            for (int p = 0; p < 2; ++p) {
                int r = a_r0 + p * 64;
                As[nxt][a_c + 0][r] = aReg[p].x;
                As[nxt][a_c + 1][r] = aReg[p].y;
                As[nxt][a_c + 2][r] = aReg[p].z;
                As[nxt][a_c + 3][r] = aReg[p].w;
            }
            cp_wait0();
        }
        __syncthreads();
    }

    float4 bv0 = make_float4(0.f, 0.f, 0.f, 0.f), bv1 = bv0;
    if (RELU) {
        bv0 = *(const float4*)(bias + colBase + tx * TN);
        bv1 = *(const float4*)(bias + colBase + tx * TN + 4);
    }
    #pragma unroll
    for (int i = 0; i < TM; i++) {
        int gr = rowBase + ty * TM + i;
        if (gr < M) {
            float s = scale[gr];
            float v[8];
            #pragma unroll
            for (int j = 0; j < 4; j++) unpack2(v[2 * j], v[2 * j + 1], accp[i][j]);
            float4 o0, o1;
            if (RELU) {
                o0.x = fmaxf(fmaf(v[0], s, bv0.x), 0.f);
                o0.y = fmaxf(fmaf(v[1], s, bv0.y), 0.f);
                o0.z = fmaxf(fmaf(v[2], s, bv0.z), 0.f);
                o0.w = fmaxf(fmaf(v[3], s, bv0.w), 0.f);
                o1.x = fmaxf(fmaf(v[4], s, bv1.x), 0.f);
                o1.y = fmaxf(fmaf(v[5], s, bv1.y), 0.f);
                o1.z = fmaxf(fmaf(v[6], s, bv1.z), 0.f);
                o1.w = fmaxf(fmaf(v[7], s, bv1.w), 0.f);
            } else {
                o0.x = v[0] * s; o0.y = v[1] * s; o0.z = v[2] * s; o0.w = v[3] * s;
                o1.x = v[4] * s; o1.y = v[5] * s; o1.z = v[6] * s; o1.w = v[7] * s;
            }
            *(float4*)(C + (size_t)gr * N + colBase + tx * TN)     = o0;
            *(float4*)(C + (size_t)gr * N + colBase + tx * TN + 4) = o1;
        }
    }
#endif  // !HAS_TCGEN05 (else: empty kernel — tcgen05 GEMM does the work)
}

// h1_f -> tf32 split is NOT needed (tc path writes split directly; fb path reads h1_f).

// ---------------- sorted-graph_id pooling ----------------
#define POOL_NB 32
__global__ void pool_accum(const float* __restrict__ h, const int* __restrict__ gid, int n)
{
    const int f = threadIdx.x;   // 128
    int base = blockIdx.x * POOL_NB;
    if (base >= n) return;
    int end = min(base + POOL_NB, n);
    float acc = 0.f; int cnt = 0;
    int cur = gid[base];
    for (int i = base; i < end; ++i) {
        int g = gid[i];
        if (g != cur) {
            atomicAdd(&g_gsum[cur * HID2 + f], acc);
            if (f == 0) atomicAdd(&g_gcnt[cur], cnt);
            acc = 0.f; cnt = 0; cur = g;
        }
        acc += h[(size_t)i * HID2 + f];
        cnt++;
    }
    atomicAdd(&g_gsum[cur * HID2 + f], acc);
    if (f == 0) atomicAdd(&g_gcnt[cur], cnt);
}

// ---------------- MLP head ----------------
__global__ void mlp_head(const float* __restrict__ Wc1, const float* __restrict__ bc1,
                         const float* __restrict__ Wc2, const float* __restrict__ bc2,
                         const float* __restrict__ Wc3, const float* __restrict__ bc3,
                         float* __restrict__ out)
{
    __shared__ float hg[N_GRAPHS * HID2];
    __shared__ float t1[N_GRAPHS * 12];
    __shared__ float t2[N_GRAPHS * 12];
    int tid = threadIdx.x;   // 768
    for (int i = tid; i < N_GRAPHS * HID2; i += 768) {
        int g = i >> 7;
        hg[i] = g_gsum[i] / (float)max(g_gcnt[g], 1);
    }
    __syncthreads();
    {
        int g = tid / 12, j = tid % 12;
        float a = bc1[j];
        #pragma unroll 8
        for (int k = 0; k < HID2; k++) a = fmaf(hg[g * HID2 + k], Wc1[k * 12 + j], a);
        t1[tid] = a;
    }
    __syncthreads();
    {
        int g = tid / 12, j = tid % 12;
        float a = bc2[j];
        #pragma unroll
        for (int k = 0; k < 12; k++) a = fmaf(t1[g * 12 + k], Wc2[k * 12 + j], a);
        t2[tid] = a;
    }
    __syncthreads();
    if (tid < N_GRAPHS * 10) {
        int g = tid / 10, j = tid % 10;
        float a = bc3[j];
        #pragma unroll
        for (int k = 0; k < 12; k++) a = fmaf(t2[g * 12 + k], Wc3[k * 10 + j], a);
        out[g * 10 + j] = a;
    }
}

// ---------------- launch ----------------
extern "C" void kernel_launch(void* const* d_in, const int* in_sizes, int n_in,
                              void* d_out, int out_size)
{
    const float* x   = (const float*)d_in[0];
    const int*   src = (const int*)  d_in[1];
    const int*   dst = (const int*)  d_in[2];
    const int*   gid = (const int*)  d_in[3];
    const float* W1  = (const float*)d_in[4];
    const float* b1  = (const float*)d_in[5];
    const float* W2  = (const float*)d_in[6];
    const float* b2  = (const float*)d_in[7];
    const float* Wc1 = (const float*)d_in[8];
    const float* bc1 = (const float*)d_in[9];
    const float* Wc2 = (const float*)d_in[10];
    const float* bc2 = (const float*)d_in[11];
    const float* Wc3 = (const float*)d_in[12];
    const float* bc3 = (const float*)d_in[13];
    float* out = (float*)d_out;

    const int n = in_sizes[0] / 128;   // nodes
    const int E = in_sizes[1];         // edges

    u32 *aggx_hi, *aggx_lo, *h1_hi, *h1_lo, *w1t_hi, *w1t_lo, *w2t_hi, *w2t_lo;
    float *aggx_f, *h1_f, *hw, *h2, *invo_p, *invi_p;
    cudaGetSymbolAddress((void**)&aggx_hi, g_aggx_hi);
    cudaGetSymbolAddress((void**)&aggx_lo, g_aggx_lo);
    cudaGetSymbolAddress((void**)&aggx_f,  g_aggx_f);
    cudaGetSymbolAddress((void**)&h1_hi, g_h1_hi);
    cudaGetSymbolAddress((void**)&h1_lo, g_h1_lo);
    cudaGetSymbolAddress((void**)&h1_f,  g_h1_f);
    cudaGetSymbolAddress((void**)&w1t_hi, g_w1t_hi);
    cudaGetSymbolAddress((void**)&w1t_lo, g_w1t_lo);
    cudaGetSymbolAddress((void**)&w2t_hi, g_w2t_hi);
    cudaGetSymbolAddress((void**)&w2t_lo, g_w2t_lo);
    cudaGetSymbolAddress((void**)&hw, g_hw);
    cudaGetSymbolAddress((void**)&h2, g_h2);
    cudaGetSymbolAddress((void**)&invo_p, g_invo);
    cudaGetSymbolAddress((void**)&invi_p, g_invi);

    cudaFuncSetAttribute(gemm_tc<4, 1>, cudaFuncAttributeMaxDynamicSharedMemorySize, GEMM_SMEM);
    cudaFuncSetAttribute(gemm_tc<8, 0>, cudaFuncAttributeMaxDynamicSharedMemorySize, GEMM_SMEM);

    zero_init<<<(n + 255) / 256, 256>>>(n);
    hist_kernel<<<(E + 255) / 256, 256>>>(src, dst, E);
    scan_rowptr<<<1, 1024>>>(n);
    make_inv<<<(n + 255) / 256, 256>>>(n);
    fill_csr<<<(E + 255) / 256, 256>>>(src, dst, E);
    wconv<<<128, 256>>>(W1, W2);

    const int mt = (n + 127) / 128;

    // Layer 1: aggx = segsum((x*invo)[src])  (split + plain)
    spmm_split<<<(n + 7) / 8, dim3(32, 8)>>>((const float4*)x, n);

    // h1 = relu(invi*(aggx@W1)+b1): tc path -> h1 split; fb path -> h1_f
    gemm_tc<4, 1><<<dim3(mt, 2), 128, GEMM_SMEM>>>(
        aggx_hi, aggx_lo, w1t_hi, w1t_lo, invi_p, b1, h1_hi, h1_lo, nullptr, n, HID1);
    gemm_fb<true><<<dim3(mt, 2), 256>>>(aggx_f, W1, invi_p, b1, h1_f, n, HID1, 128);

    // Layer 2: hw = invo * (h1 @ W2)  [n,128] — both paths write hw
    gemm_tc<8, 0><<<dim3(mt, 1), 128, GEMM_SMEM>>>(
        h1_hi, h1_lo, w2t_hi, w2t_lo, invo_p, nullptr, nullptr, nullptr, hw, n, HID2);
    gemm_fb<false><<<dim3(mt, 1), 256>>>(h1_f, W2, invo_p, nullptr, hw, n, HID2, HID1);

    // h2 = relu(invi * segsum(hw[src]) + b2)
    spmm_plain<<<(n + 7) / 8, dim3(32, 8)>>>((const float4*)hw, b2, (float4*)h2, n);

    // mean pooling (graph_id sorted)
    pool_accum<<<(n + POOL_NB - 1) / POOL_NB, 128>>>(h2, gid, n);

    // classifier head
    mlp_head<<<1, 768>>>(Wc1, bc1, Wc2, bc2, Wc3, bc3, out);
}

// round 5
// speedup vs baseline: 1.6191x; 1.0682x over previous
#include <cuda_runtime.h>
#include <cuda_bf16.h>
#include <cstdint>

#if defined(__CUDA_ARCH_FEAT_SM103_ALL) || defined(__CUDA_ARCH_FEAT_SM100_ALL) || defined(__CUDA_ARCH_FEAT_SM101_ALL)
#define HAS_TCGEN05 1
#else
#define HAS_TCGEN05 0
#endif

#define N_NODES_MAX 50048
#define N_EDGES_MAX 800000
#define N_GRAPHS 64
#define HID1 256
#define HID2 128

typedef unsigned long long u64;
typedef unsigned int u32;

// ---------------- scratch (static __device__, no allocation) ----------------
__device__ float g_aggx [N_NODES_MAX * 128];
__device__ float g_h1   [N_NODES_MAX * 256];
__device__ float g_hw   [N_NODES_MAX * 128];
__device__ float g_h2   [N_NODES_MAX * 128];
__device__ u32   g_w1t_hi[256 * 128];
__device__ u32   g_w1t_lo[256 * 128];
__device__ u32   g_w2t_hi[128 * 256];
__device__ u32   g_w2t_lo[128 * 256];
__device__ int   g_degout[N_NODES_MAX];
__device__ int   g_degin [N_NODES_MAX];
__device__ float g_invo  [N_NODES_MAX];
__device__ float g_invi  [N_NODES_MAX];
__device__ int   g_rowptr[N_NODES_MAX + 1];
__device__ int   g_cursor[N_NODES_MAX];
__device__ int   g_csr   [N_EDGES_MAX];
__device__ float g_gsum  [N_GRAPHS * HID2];
__device__ int   g_gcnt  [N_GRAPHS];

// ---------------- generic helpers ----------------
__device__ __forceinline__ u32 tf32_rna(float x) {
    u32 r; asm("cvt.rna.tf32.f32 %0, %1;" : "=r"(r) : "f"(x)); return r;
}
__device__ __forceinline__ void split_tf32(float v, u32& hi, u32& lo) {
    hi = tf32_rna(v);
    lo = tf32_rna(v - __uint_as_float(hi));
}
__device__ __forceinline__ void cp_async16(uint32_t saddr, const void* gptr) {
    asm volatile("cp.async.cg.shared.global [%0], [%1], 16;" :: "r"(saddr), "l"(gptr));
}
__device__ __forceinline__ void cp_commit()  { asm volatile("cp.async.commit_group;"); }
__device__ __forceinline__ void cp_wait0()   { asm volatile("cp.async.wait_group 0;"); }
__device__ __forceinline__ void cp_wait1()   { asm volatile("cp.async.wait_group 1;"); }

#define SWZ128(o) ((o) ^ (((o) >> 3) & 0x70))

// ---------------- preprocessing ----------------
// fused: zero counters + weight transpose/split
__global__ void init_wconv(const float* __restrict__ W1, const float* __restrict__ W2, int n) {
    int i = blockIdx.x * blockDim.x + threadIdx.x;
    if (i < n) { g_degout[i] = 0; g_degin[i] = 0; g_cursor[i] = 0; }
    if (i < N_GRAPHS * HID2) g_gsum[i] = 0.f;
    if (i < N_GRAPHS) g_gcnt[i] = 0;
    if (i < 128 * 256) {
        int k = i >> 8, nn = i & 255;
        u32 hi, lo; split_tf32(W1[i], hi, lo);
        g_w1t_hi[nn * 128 + k] = hi;
        g_w1t_lo[nn * 128 + k] = lo;
        int k2 = i >> 7, n2 = i & 127;
        u32 hi2, lo2; split_tf32(W2[i], hi2, lo2);
        g_w2t_hi[n2 * 256 + k2] = hi2;
        g_w2t_lo[n2 * 256 + k2] = lo2;
    }
}

__global__ void hist_kernel(const int* __restrict__ src, const int* __restrict__ dst, int E) {
    int e = blockIdx.x * blockDim.x + threadIdx.x;
    if (e < E) {
        atomicAdd(&g_degout[src[e]], 1);
        atomicAdd(&g_degin [dst[e]], 1);
    }
}

// fused: exclusive scan of degin -> rowptr, plus invo/invi computation
__global__ void scan_inv(int n) {
    __shared__ int warp_sums[32];
    __shared__ int s_carry;
    int tid = threadIdx.x;            // 1024
    int lane = tid & 31, wid = tid >> 5;
    if (tid == 0) s_carry = 0;
    __syncthreads();
    for (int base = 0; base < n; base += 1024) {
        int i = base + tid;
        int v = (i < n) ? g_degin[i] : 0;
        if (i < n) {
            g_invo[i] = rsqrtf((float)max(g_degout[i], 1));
            g_invi[i] = rsqrtf((float)max(v, 1));
        }
        int x = v;
        #pragma unroll
        for (int o = 1; o < 32; o <<= 1) {
            int y = __shfl_up_sync(0xFFFFFFFFu, x, o);
            if (lane >= o) x += y;
        }
        if (lane == 31) warp_sums[wid] = x;
        __syncthreads();
        if (tid < 32) {
            int w = warp_sums[tid];
            #pragma unroll
            for (int o = 1; o < 32; o <<= 1) {
                int y = __shfl_up_sync(0xFFFFFFFFu, w, o);
                if (tid >= o) w += y;
            }
            warp_sums[tid] = w;
        }
        __syncthreads();
        int prefix = (wid > 0) ? warp_sums[wid - 1] : 0;
        int total  = warp_sums[31];
        int excl   = x - v + prefix + s_carry;
        if (i < n) g_rowptr[i] = excl;
        __syncthreads();
        if (tid == 0) s_carry += total;
        __syncthreads();
    }
    if (tid == 0) g_rowptr[n] = s_carry;
}

__global__ void fill_csr(const int* __restrict__ src, const int* __restrict__ dst, int E) {
    int e = blockIdx.x * blockDim.x + threadIdx.x;
    if (e < E) {
        int d = dst[e];
        int pos = atomicAdd(&g_cursor[d], 1);
        g_csr[g_rowptr[d] + pos] = src[e];
    }
}

// ---------------- CSR gather SpMM ----------------
// spmm1: aggx[row] = sum invo[u]*X[u]
__global__ void spmm_scale(const float4* __restrict__ X, float4* __restrict__ Y, int n)
{
    int row = blockIdx.x * 8 + threadIdx.y;
    if (row >= n) return;
    int f = threadIdx.x;                 // 0..31
    int s = g_rowptr[row], e = g_rowptr[row + 1];
    float4 acc = make_float4(0.f, 0.f, 0.f, 0.f);
    int i = s;
    for (; i + 1 < e; i += 2) {
        int u0 = g_csr[i], u1 = g_csr[i + 1];
        float4 v0 = X[(size_t)u0 * 32 + f];
        float4 v1 = X[(size_t)u1 * 32 + f];
        float s0 = g_invo[u0], s1 = g_invo[u1];
        acc.x = fmaf(v0.x, s0, acc.x); acc.x = fmaf(v1.x, s1, acc.x);
        acc.y = fmaf(v0.y, s0, acc.y); acc.y = fmaf(v1.y, s1, acc.y);
        acc.z = fmaf(v0.z, s0, acc.z); acc.z = fmaf(v1.z, s1, acc.z);
        acc.w = fmaf(v0.w, s0, acc.w); acc.w = fmaf(v1.w, s1, acc.w);
    }
    if (i < e) {
        int u = g_csr[i];
        float4 v = X[(size_t)u * 32 + f];
        float s0 = g_invo[u];
        acc.x = fmaf(v.x, s0, acc.x); acc.y = fmaf(v.y, s0, acc.y);
        acc.z = fmaf(v.z, s0, acc.z); acc.w = fmaf(v.w, s0, acc.w);
    }
    Y[(size_t)row * 32 + f] = acc;
}

// spmm2: h2[row] = relu(invi[row] * sum X[u] + b)
__global__ void spmm_plain(const float4* __restrict__ X, const float* __restrict__ bias,
                           float4* __restrict__ Y, int n)
{
    int row = blockIdx.x * 8 + threadIdx.y;
    if (row >= n) return;
    int f = threadIdx.x;
    int s = g_rowptr[row], e = g_rowptr[row + 1];
    float4 acc = make_float4(0.f, 0.f, 0.f, 0.f);
    int i = s;
    for (; i + 1 < e; i += 2) {
        int u0 = g_csr[i], u1 = g_csr[i + 1];
        float4 v0 = X[(size_t)u0 * 32 + f];
        float4 v1 = X[(size_t)u1 * 32 + f];
        acc.x += v0.x + v1.x;
        acc.y += v0.y + v1.y;
        acc.z += v0.z + v1.z;
        acc.w += v0.w + v1.w;
    }
    if (i < e) {
        int u = g_csr[i];
        float4 v = X[(size_t)u * 32 + f];
        acc.x += v.x; acc.y += v.y; acc.z += v.z; acc.w += v.w;
    }
    float sc = g_invi[row];
    float4 b = *(const float4*)(bias + f * 4);
    float4 r;
    r.x = fmaxf(fmaf(acc.x, sc, b.x), 0.f);
    r.y = fmaxf(fmaf(acc.y, sc, b.y), 0.f);
    r.z = fmaxf(fmaf(acc.z, sc, b.z), 0.f);
    r.w = fmaxf(fmaf(acc.w, sc, b.w), 0.f);
    Y[(size_t)row * 32 + f] = r;
}

// ================== tcgen05 3xTF32 GEMM, pipelined ==================
// smem layout (bytes):
#define SM_TMEM 0
#define SM_MBAR 8
#define SM_BIAS 64
#define SM_AH   1024
#define SM_AL   (1024 + 16384)
#define SM_B0   (1024 + 32768)          // hi at +0, lo at +16384
#define SM_B1   (1024 + 65536)
#define GEMM_SMEM (1024 + 98304)

#if HAS_TCGEN05
static constexpr uint64_t SMEM_DESC_BASE_SW128 =
    (uint64_t(2) << 61) | (uint64_t(1) << 46) | (uint64_t(64) << 32) | (uint64_t(1) << 16);
#define MK_DESC(a) (SMEM_DESC_BASE_SW128 | ((uint64_t)((a) >> 4) & 0x3FFF))

#define TC_ALLOC(sm, n)  asm volatile("tcgen05.alloc.cta_group::1.sync.aligned.shared::cta.b32 [%0], %1;" :: "r"((uint32_t)(sm)), "r"((uint32_t)(n)) : "memory")
#define TC_RELINQ()      asm volatile("tcgen05.relinquish_alloc_permit.cta_group::1.sync.aligned;")
#define TC_DEALLOC(t, n) asm volatile("tcgen05.dealloc.cta_group::1.sync.aligned.b32 %0, %1;" :: "r"(t), "r"((uint32_t)(n)))
#define TC_COMMIT(mb)    asm volatile("tcgen05.commit.cta_group::1.mbarrier::arrive::one.shared::cluster.b64 [%0];" :: "r"((uint32_t)(mb)) : "memory")
#define TC_FENCE_AFTER() asm volatile("tcgen05.fence::after_thread_sync;" ::: "memory")
#define TC_FENCE_BEFORE() asm volatile("tcgen05.fence::before_thread_sync;" ::: "memory")
#define TC_WAIT_LD()     asm volatile("tcgen05.wait::ld.sync.aligned;" ::: "memory")
#define MBAR_INIT(mb, c) asm volatile("mbarrier.init.shared.b64 [%0], %1;" :: "r"((uint32_t)(mb)), "r"((uint32_t)(c)) : "memory")
#define MBAR_INVAL(mb)   asm volatile("mbarrier.inval.shared.b64 [%0];" :: "r"((uint32_t)(mb)) : "memory")
#define FENCE_ASYNC()    asm volatile("fence.proxy.async.shared::cta;" ::: "memory")

#define MBAR_WAIT(mb, ph) do { \
    uint32_t _mb = (uint32_t)(mb); uint32_t _p = (uint32_t)(ph); uint32_t _done; \
    asm volatile("{\n\t.reg .pred p;\n\tmbarrier.try_wait.parity.acquire.cta.shared::cta.b64 p, [%1], %2;\n\tselp.b32 %0, 1, 0, p;\n\t}" \
        : "=r"(_done) : "r"(_mb), "r"(_p) : "memory"); \
    if (!_done) { \
        asm volatile("{\n\t.reg .pred P1;\nWL_%=:\n\tmbarrier.try_wait.parity.acquire.cta.shared::cta.b64 P1, [%0], %1, 0x989680;\n\t@P1 bra.uni WD_%=;\n\tbra.uni WL_%=;\nWD_%=:\n\t}" \
            :: "r"(_mb), "r"(_p) : "memory"); \
    } \
} while (0)

#define TC_LD_X32(r, ta) \
    asm volatile("tcgen05.ld.sync.aligned.32x32b.x32.b32 " \
        "{%0, %1, %2, %3, %4, %5, %6, %7, %8, %9, %10, %11, %12, %13, %14, %15, " \
        " %16, %17, %18, %19, %20, %21, %22, %23, %24, %25, %26, %27, %28, %29, %30, %31}, [%32];" \
        : "=r"((r)[0]), "=r"((r)[1]), "=r"((r)[2]), "=r"((r)[3]), "=r"((r)[4]), "=r"((r)[5]), "=r"((r)[6]), "=r"((r)[7]), \
          "=r"((r)[8]), "=r"((r)[9]), "=r"((r)[10]), "=r"((r)[11]), "=r"((r)[12]), "=r"((r)[13]), "=r"((r)[14]), "=r"((r)[15]), \
          "=r"((r)[16]), "=r"((r)[17]), "=r"((r)[18]), "=r"((r)[19]), "=r"((r)[20]), "=r"((r)[21]), "=r"((r)[22]), "=r"((r)[23]), \
          "=r"((r)[24]), "=r"((r)[25]), "=r"((r)[26]), "=r"((r)[27]), "=r"((r)[28]), "=r"((r)[29]), "=r"((r)[30]), "=r"((r)[31]) \
        : "r"(ta))

__device__ __forceinline__ uint32_t elect_one() {
    uint32_t pred;
    asm volatile("{\n\t.reg .pred p;\n\telect.sync _|p, 0xFFFFFFFF;\n\tselp.b32 %0, 1, 0, p;\n\t}" : "=r"(pred));
    return pred;
}
__device__ __forceinline__ void mma_tf32(uint32_t d, uint64_t a, uint64_t b, uint32_t idesc, bool en) {
    uint32_t e = en ? 1u : 0u;
    asm volatile("{\n\t.reg .pred p;\n\tsetp.ne.u32 p, %5, 0;\n\t"
                 "tcgen05.mma.cta_group::1.kind::tf32 [%0], %1, %2, %3, {%4, %4, %4, %4}, p;\n\t}"
                 :: "r"(d), "l"(a), "l"(b), "r"(idesc), "r"(0u), "r"(e) : "memory");
}
#endif  // HAS_TCGEN05

// C[128x128 tile] = 3xTF32( A @ B^T ), A[M,K] fp32 (split in-kernel), B pre-split [N][K] tf32 hi/lo.
// MODE 0: O = scale[row]*acc ; MODE 1: O = relu(scale[row]*acc + bias[col]). O is fp32.
template<int KCH, int MODE>
__global__ void __launch_bounds__(128)
gemm_tc(const float* __restrict__ A,
        const u32* __restrict__ Bhi, const u32* __restrict__ Blo,
        const float* __restrict__ scale, const float* __restrict__ bias,
        float* __restrict__ O, int M, int NTOT)
{
#if HAS_TCGEN05
    extern __shared__ __align__(1024) char smem[];
    const uint32_t sb = (uint32_t)__cvta_generic_to_shared(smem);
    const int tid = threadIdx.x;
    const int wid = tid >> 5, lane = tid & 31;
    const int K = KCH * 32;
    const int rowBase = blockIdx.x * 128;
    const int colBase = blockIdx.y * 128;

    if (wid == 0) {
        TC_ALLOC(sb + SM_TMEM, 128);
        TC_RELINQ();
    }
    if (tid == 0) MBAR_INIT(sb + SM_MBAR, 1);
    if (MODE == 1) {
        *(float*)(smem + SM_BIAS + tid * 4) = bias[colBase + tid];
    }
    __syncthreads();
    uint32_t tmem;
    asm volatile("ld.shared.b32 %0, [%1];" : "=r"(tmem) : "r"(sb + SM_TMEM));

    // idesc: dtype F32, a/b TF32(2), N=128, M=128
    const uint32_t idesc = (1u << 4) | (2u << 7) | (2u << 10) | (16u << 17) | (8u << 24);

    // per-chunk thread mapping: t = tid + i*128; row = t>>3 (0..127), c16 = t&7 (16B unit)
    uint4 ahi[8], alo[8];

    // ---- load A chunk into regs (split) ----
    auto loadA = [&](int ch) {
        const int k0 = ch * 32;
        #pragma unroll
        for (int i = 0; i < 8; ++i) {
            int t = tid + i * 128;
            int row = t >> 3, c16 = t & 7;
            int gr = rowBase + row;
            float4 v = make_float4(0.f, 0.f, 0.f, 0.f);
            if (gr < M) v = *(const float4*)(A + (size_t)gr * K + k0 + c16 * 4);
            split_tf32(v.x, ahi[i].x, alo[i].x);
            split_tf32(v.y, ahi[i].y, alo[i].y);
            split_tf32(v.z, ahi[i].z, alo[i].z);
            split_tf32(v.w, ahi[i].w, alo[i].w);
        }
    };
    auto storeA = [&]() {
        #pragma unroll
        for (int i = 0; i < 8; ++i) {
            int t = tid + i * 128;
            int row = t >> 3, c16 = t & 7;
            uint32_t dofs = SWZ128((uint32_t)(row * 128 + c16 * 16));
            *(uint4*)(smem + SM_AH + dofs) = ahi[i];
            *(uint4*)(smem + SM_AL + dofs) = alo[i];
        }
    };
    auto loadB = [&](int ch, int buf) {
        const int k0 = ch * 32;
        const uint32_t bb = sb + (buf ? SM_B1 : SM_B0);
        #pragma unroll
        for (int i = 0; i < 8; ++i) {
            int t = tid + i * 128;
            int row = t >> 3, c16 = t & 7;
            uint32_t dofs = SWZ128((uint32_t)(row * 128 + c16 * 16));
            cp_async16(bb + dofs,         Bhi + (size_t)(colBase + row) * K + k0 + c16 * 4);
            cp_async16(bb + 16384 + dofs, Blo + (size_t)(colBase + row) * K + k0 + c16 * 4);
        }
        cp_commit();
    };

    // ---- prologue: chunk 0 ----
    loadB(0, 0);
    loadA(0);
    storeA();

    for (int ch = 0; ch < KCH; ++ch) {
        const int cb = ch & 1;
        const bool more = (ch + 1 < KCH);
        if (more) {
            loadB(ch + 1, cb ^ 1);
            loadA(ch + 1);
            cp_wait1();          // B(ch) complete (B(ch+1) still in flight)
        } else {
            cp_wait0();
        }
        FENCE_ASYNC();
        __syncthreads();         // A(ch) STS + B(ch) visible to async proxy

        if (wid == 0) {
            TC_FENCE_AFTER();
            if (elect_one()) {
                uint64_t dah = MK_DESC(sb + SM_AH);
                uint64_t dal = MK_DESC(sb + SM_AL);
                uint64_t dbh = MK_DESC(sb + (cb ? SM_B1 : SM_B0));
                uint64_t dbl = dbh + (16384 >> 4);
                #pragma unroll
                for (int ks = 0; ks < 4; ++ks)
                    mma_tf32(tmem, dah + ks * 2, dbh + ks * 2, idesc, !(ch == 0 && ks == 0));
                #pragma unroll
                for (int ks = 0; ks < 4; ++ks)
                    mma_tf32(tmem, dah + ks * 2, dbl + ks * 2, idesc, true);
                #pragma unroll
                for (int ks = 0; ks < 4; ++ks)
                    mma_tf32(tmem, dal + ks * 2, dbh + ks * 2, idesc, true);
                TC_COMMIT(sb + SM_MBAR);
            }
        }
        MBAR_WAIT(sb + SM_MBAR, ch & 1);   // A smem free after this
        if (more) {
            storeA();                       // stage A(ch+1)
        }
        __syncthreads();
    }
    TC_FENCE_AFTER();

    // ---- epilogue: each warp reads its 32-lane subpartition ----
    const int gr = rowBase + wid * 32 + lane;
    const float s = (gr < M) ? scale[gr] : 0.f;
    #pragma unroll
    for (int g = 0; g < 4; ++g) {
        u32 r[32];
        TC_LD_X32(r, tmem + g * 32);
        TC_WAIT_LD();
        if (gr < M) {
            float v[32];
            if (MODE == 1) {
                #pragma unroll
                for (int c = 0; c < 32; ++c) {
                    float bv = *(const float*)(smem + SM_BIAS + (g * 32 + c) * 4);
                    v[c] = fmaxf(fmaf(__uint_as_float(r[c]), s, bv), 0.f);
                }
            } else {
                #pragma unroll
                for (int c = 0; c < 32; ++c) v[c] = __uint_as_float(r[c]) * s;
            }
            size_t ofs = (size_t)gr * NTOT + colBase + g * 32;
            #pragma unroll
            for (int q = 0; q < 8; ++q)
                *(float4*)(O + ofs + q * 4) = *(float4*)&v[q * 4];
        }
    }
    TC_FENCE_BEFORE();
    __syncthreads();
    if (tid == 0) MBAR_INVAL(sb + SM_MBAR);
    __syncthreads();
    if (wid == 0) TC_DEALLOC(tmem, 128);
#endif  // HAS_TCGEN05 (non-a PTX pass compiles this empty; sm_103a cubin is what executes — proven R4)
}

// ---------------- sorted-graph_id pooling ----------------
#define POOL_NB 32
__global__ void pool_accum(const float* __restrict__ h, const int* __restrict__ gid, int n)
{
    const int f = threadIdx.x;   // 128
    int base = blockIdx.x * POOL_NB;
    if (base >= n) return;
    int end = min(base + POOL_NB, n);
    float acc = 0.f; int cnt = 0;
    int cur = gid[base];
    for (int i = base; i < end; ++i) {
        int g = gid[i];
        if (g != cur) {
            atomicAdd(&g_gsum[cur * HID2 + f], acc);
            if (f == 0) atomicAdd(&g_gcnt[cur], cnt);
            acc = 0.f; cnt = 0; cur = g;
        }
        acc += h[(size_t)i * HID2 + f];
        cnt++;
    }
    atomicAdd(&g_gsum[cur * HID2 + f], acc);
    if (f == 0) atomicAdd(&g_gcnt[cur], cnt);
}

// ---------------- MLP head ----------------
__global__ void mlp_head(const float* __restrict__ Wc1, const float* __restrict__ bc1,
                         const float* __restrict__ Wc2, const float* __restrict__ bc2,
                         const float* __restrict__ Wc3, const float* __restrict__ bc3,
                         float* __restrict__ out)
{
    __shared__ float hg[N_GRAPHS * HID2];
    __shared__ float t1[N_GRAPHS * 12];
    __shared__ float t2[N_GRAPHS * 12];
    int tid = threadIdx.x;   // 768
    for (int i = tid; i < N_GRAPHS * HID2; i += 768) {
        int g = i >> 7;
        hg[i] = g_gsum[i] / (float)max(g_gcnt[g], 1);
    }
    __syncthreads();
    {
        int g = tid / 12, j = tid % 12;
        float a = bc1[j];
        #pragma unroll 8
        for (int k = 0; k < HID2; k++) a = fmaf(hg[g * HID2 + k], Wc1[k * 12 + j], a);
        t1[tid] = a;
    }
    __syncthreads();
    {
        int g = tid / 12, j = tid % 12;
        float a = bc2[j];
        #pragma unroll
        for (int k = 0; k < 12; k++) a = fmaf(t1[g * 12 + k], Wc2[k * 12 + j], a);
        t2[tid] = a;
    }
    __syncthreads();
    if (tid < N_GRAPHS * 10) {
        int g = tid / 10, j = tid % 10;
        float a = bc3[j];
        #pragma unroll
        for (int k = 0; k < 12; k++) a = fmaf(t2[g * 12 + k], Wc3[k * 10 + j], a);
        out[g * 10 + j] = a;
    }
}

// ---------------- launch ----------------
extern "C" void kernel_launch(void* const* d_in, const int* in_sizes, int n_in,
                              void* d_out, int out_size)
{
    const float* x   = (const float*)d_in[0];
    const int*   src = (const int*)  d_in[1];
    const int*   dst = (const int*)  d_in[2];
    const int*   gid = (const int*)  d_in[3];
    const float* W1  = (const float*)d_in[4];
    const float* b1  = (const float*)d_in[5];
    const float* W2  = (const float*)d_in[6];
    const float* b2  = (const float*)d_in[7];
    const float* Wc1 = (const float*)d_in[8];
    const float* bc1 = (const float*)d_in[9];
    const float* Wc2 = (const float*)d_in[10];
    const float* bc2 = (const float*)d_in[11];
    const float* Wc3 = (const float*)d_in[12];
    const float* bc3 = (const float*)d_in[13];
    float* out = (float*)d_out;

    const int n = in_sizes[0] / 128;   // nodes
    const int E = in_sizes[1];         // edges

    u32 *w1t_hi, *w1t_lo, *w2t_hi, *w2t_lo;
    float *aggx, *h1, *hw, *h2, *invo_p, *invi_p;
    cudaGetSymbolAddress((void**)&w1t_hi, g_w1t_hi);
    cudaGetSymbolAddress((void**)&w1t_lo, g_w1t_lo);
    cudaGetSymbolAddress((void**)&w2t_hi, g_w2t_hi);
    cudaGetSymbolAddress((void**)&w2t_lo, g_w2t_lo);
    cudaGetSymbolAddress((void**)&aggx, g_aggx);
    cudaGetSymbolAddress((void**)&h1, g_h1);
    cudaGetSymbolAddress((void**)&hw, g_hw);
    cudaGetSymbolAddress((void**)&h2, g_h2);
    cudaGetSymbolAddress((void**)&invo_p, g_invo);
    cudaGetSymbolAddress((void**)&invi_p, g_invi);

    cudaFuncSetAttribute(gemm_tc<4, 1>, cudaFuncAttributeMaxDynamicSharedMemorySize, GEMM_SMEM);
    cudaFuncSetAttribute(gemm_tc<8, 0>, cudaFuncAttributeMaxDynamicSharedMemorySize, GEMM_SMEM);

    init_wconv<<<(n + 255) / 256, 256>>>(W1, W2, n);
    hist_kernel<<<(E + 255) / 256, 256>>>(src, dst, E);
    scan_inv<<<1, 1024>>>(n);
    fill_csr<<<(E + 255) / 256, 256>>>(src, dst, E);

    const int mt = (n + 127) / 128;

    // Layer 1: aggx = segsum((x*invo)[src])  [n,128]
    spmm_scale<<<(n + 7) / 8, dim3(32, 8)>>>((const float4*)x, (float4*)aggx, n);
    // h1 = relu(invi * (aggx @ W1) + b1)  [n,256]
    gemm_tc<4, 1><<<dim3(mt, 2), 128, GEMM_SMEM>>>(aggx, w1t_hi, w1t_lo, invi_p, b1, h1, n, HID1);

    // Layer 2: hw = invo * (h1 @ W2)  [n,128]
    gemm_tc<8, 0><<<dim3(mt, 1), 128, GEMM_SMEM>>>(h1, w2t_hi, w2t_lo, invo_p, nullptr, hw, n, HID2);
    // h2 = relu(invi * segsum(hw[src]) + b2)  [n,128]
    spmm_plain<<<(n + 7) / 8, dim3(32, 8)>>>((const float4*)hw, b2, (float4*)h2, n);

    // mean pooling (graph_id sorted)
    pool_accum<<<(n + POOL_NB - 1) / POOL_NB, 128>>>(h2, gid, n);

    // classifier head
    mlp_head<<<1, 768>>>(Wc1, bc1, Wc2, bc2, Wc3, bc3, out);
}

// round 6
// speedup vs baseline: 1.9683x; 1.2157x over previous
#include <cuda_runtime.h>
#include <cuda_bf16.h>
#include <cstdint>

#if defined(__CUDA_ARCH_FEAT_SM103_ALL) || defined(__CUDA_ARCH_FEAT_SM100_ALL) || defined(__CUDA_ARCH_FEAT_SM101_ALL)
#define HAS_TCGEN05 1
#else
#define HAS_TCGEN05 0
#endif

#define N_NODES_MAX 50048
#define N_EDGES_MAX 800000
#define N_GRAPHS 64
#define HID1 256
#define HID2 128
#define SCAN_B 1024

typedef unsigned long long u64;
typedef unsigned int u32;

// ---------------- scratch (static __device__, no allocation) ----------------
__device__ float g_aggx [N_NODES_MAX * 128];
__device__ float g_h1   [N_NODES_MAX * 256];
__device__ float g_hw   [N_NODES_MAX * 128];
__device__ float g_h2   [N_NODES_MAX * 128];
__device__ u32   g_w1t_hi[256 * 128];
__device__ u32   g_w1t_lo[256 * 128];
__device__ u32   g_w2t_hi[128 * 256];
__device__ u32   g_w2t_lo[128 * 256];
__device__ int   g_degout[N_NODES_MAX];
__device__ int   g_degin [N_NODES_MAX];
__device__ float g_invo  [N_NODES_MAX];
__device__ float g_invi  [N_NODES_MAX];
__device__ int   g_rowptr[N_NODES_MAX + 1];
__device__ int   g_cursor[N_NODES_MAX];
__device__ int   g_btot  [64];
__device__ int   g_boff  [64];
__device__ int   g_csr   [N_EDGES_MAX];
__device__ float g_gsum  [N_GRAPHS * HID2];
__device__ int   g_gcnt  [N_GRAPHS];

// ---------------- generic helpers ----------------
__device__ __forceinline__ u32 tf32_rna(float x) {
    u32 r; asm("cvt.rna.tf32.f32 %0, %1;" : "=r"(r) : "f"(x)); return r;
}
__device__ __forceinline__ void split_tf32(float v, u32& hi, u32& lo) {
    hi = tf32_rna(v);
    lo = tf32_rna(v - __uint_as_float(hi));
}
__device__ __forceinline__ void cp_async16(uint32_t saddr, const void* gptr) {
    asm volatile("cp.async.cg.shared.global [%0], [%1], 16;" :: "r"(saddr), "l"(gptr));
}
__device__ __forceinline__ void cp_commit()  { asm volatile("cp.async.commit_group;"); }
__device__ __forceinline__ void cp_wait0()   { asm volatile("cp.async.wait_group 0;"); }
__device__ __forceinline__ void cp_wait1()   { asm volatile("cp.async.wait_group 1;"); }

#define SWZ128(o) ((o) ^ (((o) >> 3) & 0x70))

// ---------------- preprocessing ----------------
// fused: zero counters + weight transpose/split
__global__ void init_wconv(const float* __restrict__ W1, const float* __restrict__ W2, int n) {
    int i = blockIdx.x * blockDim.x + threadIdx.x;
    if (i < n) { g_degout[i] = 0; g_degin[i] = 0; }
    if (i < N_GRAPHS * HID2) g_gsum[i] = 0.f;
    if (i < N_GRAPHS) g_gcnt[i] = 0;
    if (i < 128 * 256) {
        int k = i >> 8, nn = i & 255;
        u32 hi, lo; split_tf32(W1[i], hi, lo);
        g_w1t_hi[nn * 128 + k] = hi;
        g_w1t_lo[nn * 128 + k] = lo;
        int k2 = i >> 7, n2 = i & 127;
        u32 hi2, lo2; split_tf32(W2[i], hi2, lo2);
        g_w2t_hi[n2 * 256 + k2] = hi2;
        g_w2t_lo[n2 * 256 + k2] = lo2;
    }
}

__global__ void hist_kernel(const int* __restrict__ src, const int* __restrict__ dst, int E) {
    int e = blockIdx.x * blockDim.x + threadIdx.x;
    if (e < E) {
        atomicAdd(&g_degout[src[e]], 1);
        atomicAdd(&g_degin [dst[e]], 1);
    }
}

// scan phase 1: per-block exclusive scan of degin -> rowptr (local), block totals; invo/invi
__global__ void scan_part(int n) {
    __shared__ int warp_sums[32];
    int tid = threadIdx.x;            // 1024
    int lane = tid & 31, wid = tid >> 5;
    int i = blockIdx.x * SCAN_B + tid;
    int v = (i < n) ? g_degin[i] : 0;
    if (i < n) {
        g_invo[i] = rsqrtf((float)max(g_degout[i], 1));
        g_invi[i] = rsqrtf((float)max(v, 1));
    }
    int x = v;
    #pragma unroll
    for (int o = 1; o < 32; o <<= 1) {
        int y = __shfl_up_sync(0xFFFFFFFFu, x, o);
        if (lane >= o) x += y;
    }
    if (lane == 31) warp_sums[wid] = x;
    __syncthreads();
    if (tid < 32) {
        int w = warp_sums[tid];
        #pragma unroll
        for (int o = 1; o < 32; o <<= 1) {
            int y = __shfl_up_sync(0xFFFFFFFFu, w, o);
            if (tid >= o) w += y;
        }
        warp_sums[tid] = w;
    }
    __syncthreads();
    int prefix = (wid > 0) ? warp_sums[wid - 1] : 0;
    if (i < n) g_rowptr[i] = x - v + prefix;           // block-local exclusive
    if (tid == 1023) g_btot[blockIdx.x] = warp_sums[31];
}

// scan phase 2: exclusive scan of block totals (<=64 blocks)
__global__ void scan_top(int nb) {
    int tid = threadIdx.x;   // 64
    int v = (tid < nb) ? g_btot[tid] : 0;
    int x = v;
    #pragma unroll
    for (int o = 1; o < 64; o <<= 1) {
        int y = __shfl_up_sync(0xFFFFFFFFu, x, o & 31);
        if ((tid & 31) >= (o & 31) && o < 32) x += y;
    }
    // simple: do it with shared memory to avoid cross-warp shuffle complexity
    __shared__ int s[64];
    s[tid] = v;
    __syncthreads();
    if (tid == 0) {
        int acc = 0;
        for (int b = 0; b < nb; ++b) { int t = s[b]; s[b] = acc; acc += t; }
        s[63] = 0;  // unused slot safe
        g_btot[63] = acc;   // total edges (diagnostic)
    }
    __syncthreads();
    if (tid < nb) g_boff[tid] = s[tid];
}

// scan phase 3: add block offsets; cursor = rowptr; set rowptr[n]
__global__ void scan_fin(int n, int E) {
    int i = blockIdx.x * SCAN_B + threadIdx.x;
    if (i < n) {
        int r = g_rowptr[i] + g_boff[blockIdx.x];
        g_rowptr[i] = r;
        g_cursor[i] = r;
    }
    if (i == 0) g_rowptr[n] = E;
}

__global__ void fill_csr(const int* __restrict__ src, const int* __restrict__ dst, int E) {
    int e = blockIdx.x * blockDim.x + threadIdx.x;
    if (e < E) {
        int pos = atomicAdd(&g_cursor[dst[e]], 1);
        g_csr[pos] = src[e];
    }
}

// ---------------- CSR gather SpMM ----------------
// spmm1: aggx[row] = sum invo[u]*X[u]
__global__ void spmm_scale(const float4* __restrict__ X, float4* __restrict__ Y, int n)
{
    int row = blockIdx.x * 8 + threadIdx.y;
    if (row >= n) return;
    int f = threadIdx.x;                 // 0..31
    int s = g_rowptr[row], e = g_rowptr[row + 1];
    float4 acc = make_float4(0.f, 0.f, 0.f, 0.f);
    int i = s;
    for (; i + 3 < e; i += 4) {
        int u0 = g_csr[i], u1 = g_csr[i + 1], u2 = g_csr[i + 2], u3 = g_csr[i + 3];
        float4 v0 = X[(size_t)u0 * 32 + f];
        float4 v1 = X[(size_t)u1 * 32 + f];
        float4 v2 = X[(size_t)u2 * 32 + f];
        float4 v3 = X[(size_t)u3 * 32 + f];
        float s0 = g_invo[u0], s1 = g_invo[u1], s2 = g_invo[u2], s3 = g_invo[u3];
        acc.x = fmaf(v0.x, s0, acc.x); acc.x = fmaf(v1.x, s1, acc.x);
        acc.x = fmaf(v2.x, s2, acc.x); acc.x = fmaf(v3.x, s3, acc.x);
        acc.y = fmaf(v0.y, s0, acc.y); acc.y = fmaf(v1.y, s1, acc.y);
        acc.y = fmaf(v2.y, s2, acc.y); acc.y = fmaf(v3.y, s3, acc.y);
        acc.z = fmaf(v0.z, s0, acc.z); acc.z = fmaf(v1.z, s1, acc.z);
        acc.z = fmaf(v2.z, s2, acc.z); acc.z = fmaf(v3.z, s3, acc.z);
        acc.w = fmaf(v0.w, s0, acc.w); acc.w = fmaf(v1.w, s1, acc.w);
        acc.w = fmaf(v2.w, s2, acc.w); acc.w = fmaf(v3.w, s3, acc.w);
    }
    for (; i < e; ++i) {
        int u = g_csr[i];
        float4 v = X[(size_t)u * 32 + f];
        float s0 = g_invo[u];
        acc.x = fmaf(v.x, s0, acc.x); acc.y = fmaf(v.y, s0, acc.y);
        acc.z = fmaf(v.z, s0, acc.z); acc.w = fmaf(v.w, s0, acc.w);
    }
    Y[(size_t)row * 32 + f] = acc;
}

// spmm2: h2[row] = relu(invi[row] * sum X[u] + b)
__global__ void spmm_plain(const float4* __restrict__ X, const float* __restrict__ bias,
                           float4* __restrict__ Y, int n)
{
    int row = blockIdx.x * 8 + threadIdx.y;
    if (row >= n) return;
    int f = threadIdx.x;
    int s = g_rowptr[row], e = g_rowptr[row + 1];
    float4 acc = make_float4(0.f, 0.f, 0.f, 0.f);
    int i = s;
    for (; i + 3 < e; i += 4) {
        int u0 = g_csr[i], u1 = g_csr[i + 1], u2 = g_csr[i + 2], u3 = g_csr[i + 3];
        float4 v0 = X[(size_t)u0 * 32 + f];
        float4 v1 = X[(size_t)u1 * 32 + f];
        float4 v2 = X[(size_t)u2 * 32 + f];
        float4 v3 = X[(size_t)u3 * 32 + f];
        acc.x += (v0.x + v1.x) + (v2.x + v3.x);
        acc.y += (v0.y + v1.y) + (v2.y + v3.y);
        acc.z += (v0.z + v1.z) + (v2.z + v3.z);
        acc.w += (v0.w + v1.w) + (v2.w + v3.w);
    }
    for (; i < e; ++i) {
        int u = g_csr[i];
        float4 v = X[(size_t)u * 32 + f];
        acc.x += v.x; acc.y += v.y; acc.z += v.z; acc.w += v.w;
    }
    float sc = g_invi[row];
    float4 b = *(const float4*)(bias + f * 4);
    float4 r;
    r.x = fmaxf(fmaf(acc.x, sc, b.x), 0.f);
    r.y = fmaxf(fmaf(acc.y, sc, b.y), 0.f);
    r.z = fmaxf(fmaf(acc.z, sc, b.z), 0.f);
    r.w = fmaxf(fmaf(acc.w, sc, b.w), 0.f);
    Y[(size_t)row * 32 + f] = r;
}

// ================== tcgen05 3xTF32 GEMM, pipelined (unchanged from R5 — passing) ==================
#define SM_TMEM 0
#define SM_MBAR 8
#define SM_BIAS 64
#define SM_AH   1024
#define SM_AL   (1024 + 16384)
#define SM_B0   (1024 + 32768)          // hi at +0, lo at +16384
#define SM_B1   (1024 + 65536)
#define GEMM_SMEM (1024 + 98304)

#if HAS_TCGEN05
static constexpr uint64_t SMEM_DESC_BASE_SW128 =
    (uint64_t(2) << 61) | (uint64_t(1) << 46) | (uint64_t(64) << 32) | (uint64_t(1) << 16);
#define MK_DESC(a) (SMEM_DESC_BASE_SW128 | ((uint64_t)((a) >> 4) & 0x3FFF))

#define TC_ALLOC(sm, n)  asm volatile("tcgen05.alloc.cta_group::1.sync.aligned.shared::cta.b32 [%0], %1;" :: "r"((uint32_t)(sm)), "r"((uint32_t)(n)) : "memory")
#define TC_RELINQ()      asm volatile("tcgen05.relinquish_alloc_permit.cta_group::1.sync.aligned;")
#define TC_DEALLOC(t, n) asm volatile("tcgen05.dealloc.cta_group::1.sync.aligned.b32 %0, %1;" :: "r"(t), "r"((uint32_t)(n)))
#define TC_COMMIT(mb)    asm volatile("tcgen05.commit.cta_group::1.mbarrier::arrive::one.shared::cluster.b64 [%0];" :: "r"((uint32_t)(mb)) : "memory")
#define TC_FENCE_AFTER() asm volatile("tcgen05.fence::after_thread_sync;" ::: "memory")
#define TC_FENCE_BEFORE() asm volatile("tcgen05.fence::before_thread_sync;" ::: "memory")
#define TC_WAIT_LD()     asm volatile("tcgen05.wait::ld.sync.aligned;" ::: "memory")
#define MBAR_INIT(mb, c) asm volatile("mbarrier.init.shared.b64 [%0], %1;" :: "r"((uint32_t)(mb)), "r"((uint32_t)(c)) : "memory")
#define MBAR_INVAL(mb)   asm volatile("mbarrier.inval.shared.b64 [%0];" :: "r"((uint32_t)(mb)) : "memory")
#define FENCE_ASYNC()    asm volatile("fence.proxy.async.shared::cta;" ::: "memory")

#define MBAR_WAIT(mb, ph) do { \
    uint32_t _mb = (uint32_t)(mb); uint32_t _p = (uint32_t)(ph); uint32_t _done; \
    asm volatile("{\n\t.reg .pred p;\n\tmbarrier.try_wait.parity.acquire.cta.shared::cta.b64 p, [%1], %2;\n\tselp.b32 %0, 1, 0, p;\n\t}" \
        : "=r"(_done) : "r"(_mb), "r"(_p) : "memory"); \
    if (!_done) { \
        asm volatile("{\n\t.reg .pred P1;\nWL_%=:\n\tmbarrier.try_wait.parity.acquire.cta.shared::cta.b64 P1, [%0], %1, 0x989680;\n\t@P1 bra.uni WD_%=;\n\tbra.uni WL_%=;\nWD_%=:\n\t}" \
            :: "r"(_mb), "r"(_p) : "memory"); \
    } \
} while (0)

#define TC_LD_X32(r, ta) \
    asm volatile("tcgen05.ld.sync.aligned.32x32b.x32.b32 " \
        "{%0, %1, %2, %3, %4, %5, %6, %7, %8, %9, %10, %11, %12, %13, %14, %15, " \
        " %16, %17, %18, %19, %20, %21, %22, %23, %24, %25, %26, %27, %28, %29, %30, %31}, [%32];" \
        : "=r"((r)[0]), "=r"((r)[1]), "=r"((r)[2]), "=r"((r)[3]), "=r"((r)[4]), "=r"((r)[5]), "=r"((r)[6]), "=r"((r)[7]), \
          "=r"((r)[8]), "=r"((r)[9]), "=r"((r)[10]), "=r"((r)[11]), "=r"((r)[12]), "=r"((r)[13]), "=r"((r)[14]), "=r"((r)[15]), \
          "=r"((r)[16]), "=r"((r)[17]), "=r"((r)[18]), "=r"((r)[19]), "=r"((r)[20]), "=r"((r)[21]), "=r"((r)[22]), "=r"((r)[23]), \
          "=r"((r)[24]), "=r"((r)[25]), "=r"((r)[26]), "=r"((r)[27]), "=r"((r)[28]), "=r"((r)[29]), "=r"((r)[30]), "=r"((r)[31]) \
        : "r"(ta))

__device__ __forceinline__ uint32_t elect_one() {
    uint32_t pred;
    asm volatile("{\n\t.reg .pred p;\n\telect.sync _|p, 0xFFFFFFFF;\n\tselp.b32 %0, 1, 0, p;\n\t}" : "=r"(pred));
    return pred;
}
__device__ __forceinline__ void mma_tf32(uint32_t d, uint64_t a, uint64_t b, uint32_t idesc, bool en) {
    uint32_t e = en ? 1u : 0u;
    asm volatile("{\n\t.reg .pred p;\n\tsetp.ne.u32 p, %5, 0;\n\t"
                 "tcgen05.mma.cta_group::1.kind::tf32 [%0], %1, %2, %3, {%4, %4, %4, %4}, p;\n\t}"
                 :: "r"(d), "l"(a), "l"(b), "r"(idesc), "r"(0u), "r"(e) : "memory");
}
#endif  // HAS_TCGEN05

template<int KCH, int MODE>
__global__ void __launch_bounds__(128)
gemm_tc(const float* __restrict__ A,
        const u32* __restrict__ Bhi, const u32* __restrict__ Blo,
        const float* __restrict__ scale, const float* __restrict__ bias,
        float* __restrict__ O, int M, int NTOT)
{
#if HAS_TCGEN05
    extern __shared__ __align__(1024) char smem[];
    const uint32_t sb = (uint32_t)__cvta_generic_to_shared(smem);
    const int tid = threadIdx.x;
    const int wid = tid >> 5, lane = tid & 31;
    const int K = KCH * 32;
    const int rowBase = blockIdx.x * 128;
    const int colBase = blockIdx.y * 128;

    if (wid == 0) {
        TC_ALLOC(sb + SM_TMEM, 128);
        TC_RELINQ();
    }
    if (tid == 0) MBAR_INIT(sb + SM_MBAR, 1);
    if (MODE == 1) {
        *(float*)(smem + SM_BIAS + tid * 4) = bias[colBase + tid];
    }
    __syncthreads();
    uint32_t tmem;
    asm volatile("ld.shared.b32 %0, [%1];" : "=r"(tmem) : "r"(sb + SM_TMEM));

    const uint32_t idesc = (1u << 4) | (2u << 7) | (2u << 10) | (16u << 17) | (8u << 24);

    uint4 ahi[8], alo[8];

    auto loadA = [&](int ch) {
        const int k0 = ch * 32;
        #pragma unroll
        for (int i = 0; i < 8; ++i) {
            int t = tid + i * 128;
            int row = t >> 3, c16 = t & 7;
            int gr = rowBase + row;
            float4 v = make_float4(0.f, 0.f, 0.f, 0.f);
            if (gr < M) v = *(const float4*)(A + (size_t)gr * K + k0 + c16 * 4);
            split_tf32(v.x, ahi[i].x, alo[i].x);
            split_tf32(v.y, ahi[i].y, alo[i].y);
            split_tf32(v.z, ahi[i].z, alo[i].z);
            split_tf32(v.w, ahi[i].w, alo[i].w);
        }
    };
    auto storeA = [&]() {
        #pragma unroll
        for (int i = 0; i < 8; ++i) {
            int t = tid + i * 128;
            int row = t >> 3, c16 = t & 7;
            uint32_t dofs = SWZ128((uint32_t)(row * 128 + c16 * 16));
            *(uint4*)(smem + SM_AH + dofs) = ahi[i];
            *(uint4*)(smem + SM_AL + dofs) = alo[i];
        }
    };
    auto loadB = [&](int ch, int buf) {
        const int k0 = ch * 32;
        const uint32_t bb = sb + (buf ? SM_B1 : SM_B0);
        #pragma unroll
        for (int i = 0; i < 8; ++i) {
            int t = tid + i * 128;
            int row = t >> 3, c16 = t & 7;
            uint32_t dofs = SWZ128((uint32_t)(row * 128 + c16 * 16));
            cp_async16(bb + dofs,         Bhi + (size_t)(colBase + row) * K + k0 + c16 * 4);
            cp_async16(bb + 16384 + dofs, Blo + (size_t)(colBase + row) * K + k0 + c16 * 4);
        }
        cp_commit();
    };

    loadB(0, 0);
    loadA(0);
    storeA();

    for (int ch = 0; ch < KCH; ++ch) {
        const int cb = ch & 1;
        const bool more = (ch + 1 < KCH);
        if (more) {
            loadB(ch + 1, cb ^ 1);
            loadA(ch + 1);
            cp_wait1();
        } else {
            cp_wait0();
        }
        FENCE_ASYNC();
        __syncthreads();

        if (wid == 0) {
            TC_FENCE_AFTER();
            if (elect_one()) {
                uint64_t dah = MK_DESC(sb + SM_AH);
                uint64_t dal = MK_DESC(sb + SM_AL);
                uint64_t dbh = MK_DESC(sb + (cb ? SM_B1 : SM_B0));
                uint64_t dbl = dbh + (16384 >> 4);
                #pragma unroll
                for (int ks = 0; ks < 4; ++ks)
                    mma_tf32(tmem, dah + ks * 2, dbh + ks * 2, idesc, !(ch == 0 && ks == 0));
                #pragma unroll
                for (int ks = 0; ks < 4; ++ks)
                    mma_tf32(tmem, dah + ks * 2, dbl + ks * 2, idesc, true);
                #pragma unroll
                for (int ks = 0; ks < 4; ++ks)
                    mma_tf32(tmem, dal + ks * 2, dbh + ks * 2, idesc, true);
                TC_COMMIT(sb + SM_MBAR);
            }
        }
        MBAR_WAIT(sb + SM_MBAR, ch & 1);
        if (more) {
            storeA();
        }
        __syncthreads();
    }
    TC_FENCE_AFTER();

    const int gr = rowBase + wid * 32 + lane;
    const float s = (gr < M) ? scale[gr] : 0.f;
    #pragma unroll
    for (int g = 0; g < 4; ++g) {
        u32 r[32];
        TC_LD_X32(r, tmem + g * 32);
        TC_WAIT_LD();
        if (gr < M) {
            float v[32];
            if (MODE == 1) {
                #pragma unroll
                for (int c = 0; c < 32; ++c) {
                    float bv = *(const float*)(smem + SM_BIAS + (g * 32 + c) * 4);
                    v[c] = fmaxf(fmaf(__uint_as_float(r[c]), s, bv), 0.f);
                }
            } else {
                #pragma unroll
                for (int c = 0; c < 32; ++c) v[c] = __uint_as_float(r[c]) * s;
            }
            size_t ofs = (size_t)gr * NTOT + colBase + g * 32;
            #pragma unroll
            for (int q = 0; q < 8; ++q)
                *(float4*)(O + ofs + q * 4) = *(float4*)&v[q * 4];
        }
    }
    TC_FENCE_BEFORE();
    __syncthreads();
    if (tid == 0) MBAR_INVAL(sb + SM_MBAR);
    __syncthreads();
    if (wid == 0) TC_DEALLOC(tmem, 128);
#endif
}

// ---------------- sorted-graph_id pooling ----------------
#define POOL_NB 16
__global__ void pool_accum(const float* __restrict__ h, const int* __restrict__ gid, int n)
{
    const int f = threadIdx.x;   // 128
    int base = blockIdx.x * POOL_NB;
    if (base >= n) return;
    int end = min(base + POOL_NB, n);
    float acc = 0.f; int cnt = 0;
    int cur = gid[base];
    for (int i = base; i < end; ++i) {
        int g = gid[i];
        if (g != cur) {
            atomicAdd(&g_gsum[cur * HID2 + f], acc);
            if (f == 0) atomicAdd(&g_gcnt[cur], cnt);
            acc = 0.f; cnt = 0; cur = g;
        }
        acc += h[(size_t)i * HID2 + f];
        cnt++;
    }
    atomicAdd(&g_gsum[cur * HID2 + f], acc);
    if (f == 0) atomicAdd(&g_gcnt[cur], cnt);
}

// ---------------- MLP head ----------------
__global__ void mlp_head(const float* __restrict__ Wc1, const float* __restrict__ bc1,
                         const float* __restrict__ Wc2, const float* __restrict__ bc2,
                         const float* __restrict__ Wc3, const float* __restrict__ bc3,
                         float* __restrict__ out)
{
    __shared__ float hg[N_GRAPHS * HID2];
    __shared__ float t1[N_GRAPHS * 12];
    __shared__ float t2[N_GRAPHS * 12];
    int tid = threadIdx.x;   // 768
    for (int i = tid; i < N_GRAPHS * HID2; i += 768) {
        int g = i >> 7;
        hg[i] = g_gsum[i] / (float)max(g_gcnt[g], 1);
    }
    __syncthreads();
    {
        int g = tid / 12, j = tid % 12;
        float a = bc1[j];
        #pragma unroll 8
        for (int k = 0; k < HID2; k++) a = fmaf(hg[g * HID2 + k], Wc1[k * 12 + j], a);
        t1[tid] = a;
    }
    __syncthreads();
    {
        int g = tid / 12, j = tid % 12;
        float a = bc2[j];
        #pragma unroll
        for (int k = 0; k < 12; k++) a = fmaf(t1[g * 12 + k], Wc2[k * 12 + j], a);
        t2[tid] = a;
    }
    __syncthreads();
    if (tid < N_GRAPHS * 10) {
        int g = tid / 10, j = tid % 10;
        float a = bc3[j];
        #pragma unroll
        for (int k = 0; k < 12; k++) a = fmaf(t2[g * 12 + k], Wc3[k * 10 + j], a);
        out[g * 10 + j] = a;
    }
}

// ---------------- launch ----------------
extern "C" void kernel_launch(void* const* d_in, const int* in_sizes, int n_in,
                              void* d_out, int out_size)
{
    const float* x   = (const float*)d_in[0];
    const int*   src = (const int*)  d_in[1];
    const int*   dst = (const int*)  d_in[2];
    const int*   gid = (const int*)  d_in[3];
    const float* W1  = (const float*)d_in[4];
    const float* b1  = (const float*)d_in[5];
    const float* W2  = (const float*)d_in[6];
    const float* b2  = (const float*)d_in[7];
    const float* Wc1 = (const float*)d_in[8];
    const float* bc1 = (const float*)d_in[9];
    const float* Wc2 = (const float*)d_in[10];
    const float* bc2 = (const float*)d_in[11];
    const float* Wc3 = (const float*)d_in[12];
    const float* bc3 = (const float*)d_in[13];
    float* out = (float*)d_out;

    const int n = in_sizes[0] / 128;   // nodes
    const int E = in_sizes[1];         // edges
    const int nb = (n + SCAN_B - 1) / SCAN_B;

    u32 *w1t_hi, *w1t_lo, *w2t_hi, *w2t_lo;
    float *aggx, *h1, *hw, *h2, *invo_p, *invi_p;
    cudaGetSymbolAddress((void**)&w1t_hi, g_w1t_hi);
    cudaGetSymbolAddress((void**)&w1t_lo, g_w1t_lo);
    cudaGetSymbolAddress((void**)&w2t_hi, g_w2t_hi);
    cudaGetSymbolAddress((void**)&w2t_lo, g_w2t_lo);
    cudaGetSymbolAddress((void**)&aggx, g_aggx);
    cudaGetSymbolAddress((void**)&h1, g_h1);
    cudaGetSymbolAddress((void**)&hw, g_hw);
    cudaGetSymbolAddress((void**)&h2, g_h2);
    cudaGetSymbolAddress((void**)&invo_p, g_invo);
    cudaGetSymbolAddress((void**)&invi_p, g_invi);

    cudaFuncSetAttribute(gemm_tc<4, 1>, cudaFuncAttributeMaxDynamicSharedMemorySize, GEMM_SMEM);
    cudaFuncSetAttribute(gemm_tc<8, 0>, cudaFuncAttributeMaxDynamicSharedMemorySize, GEMM_SMEM);

    init_wconv<<<(n + 255) / 256, 256>>>(W1, W2, n);
    hist_kernel<<<(E + 255) / 256, 256>>>(src, dst, E);
    scan_part<<<nb, SCAN_B>>>(n);
    scan_top<<<1, 64>>>(nb);
    scan_fin<<<nb, SCAN_B>>>(n, E);
    fill_csr<<<(E + 255) / 256, 256>>>(src, dst, E);

    const int mt = (n + 127) / 128;

    // Layer 1: aggx = segsum((x*invo)[src])  [n,128]
    spmm_scale<<<(n + 7) / 8, dim3(32, 8)>>>((const float4*)x, (float4*)aggx, n);
    // h1 = relu(invi * (aggx @ W1) + b1)  [n,256]
    gemm_tc<4, 1><<<dim3(mt, 2), 128, GEMM_SMEM>>>(aggx, w1t_hi, w1t_lo, invi_p, b1, h1, n, HID1);

    // Layer 2: hw = invo * (h1 @ W2)  [n,128]
    gemm_tc<8, 0><<<dim3(mt, 1), 128, GEMM_SMEM>>>(h1, w2t_hi, w2t_lo, invo_p, nullptr, hw, n, HID2);
    // h2 = relu(invi * segsum(hw[src]) + b2)  [n,128]
    spmm_plain<<<(n + 7) / 8, dim3(32, 8)>>>((const float4*)hw, b2, (float4*)h2, n);

    // mean pooling (graph_id sorted)
    pool_accum<<<(n + POOL_NB - 1) / POOL_NB, 128>>>(h2, gid, n);

    // classifier head
    mlp_head<<<1, 768>>>(Wc1, bc1, Wc2, bc2, Wc3, bc3, out);
}